// round 1
// baseline (speedup 1.0000x reference)
#include <cuda_runtime.h>
#include <math.h>

#define N_ROWS 32768
#define D_IN   768
#define D_H1   2048
#define D_H2   1024
#define D_E    64
#define N_CODE 256
#define N_PAIR 4096
#define N_TRIP 8192

// Output layout (float32, concatenated in reference return order):
// out[32768*768], vq_loss[1], idx[32768], x_q_st[32768*64], outer[1], trip[1], qd[1]
#define VQ_OFF    25165824
#define IDX_OFF   25165825
#define XQ_OFF    25198593
#define OUTER_OFF 27295745
#define TRIP_OFF  27295746
#define QD_OFF    27295747

// -------- scratch (device globals: allocation-free) --------
__device__ float g_h1[(size_t)N_ROWS * D_H1];   // 256 MB
__device__ float g_h2[(size_t)N_ROWS * D_H2];   // 128 MB
__device__ float g_z [(size_t)N_ROWS * D_E];
__device__ float g_qz[(size_t)N_ROWS * D_E];
__device__ float g_xq[(size_t)N_ROWS * D_E];    // aligned copy of x_q for dec GEMM
__device__ float g_cbn[N_CODE * D_E];
__device__ float g_G  [N_CODE * N_CODE];
__device__ float g_lse[N_CODE];
__device__ int   g_idx[N_ROWS];
__device__ int   g_cnt[N_CODE];
__device__ double g_acc[4];  // 0: vq sum, 1: cos sum, 2: trip sum, 3: outer sum

// -------------------------------------------------------------------------
__global__ void init_kernel() {
    int t = threadIdx.x;
    if (t < 4) g_acc[t] = 0.0;
    if (t < N_CODE) g_cnt[t] = 0;
}

// -------------------------------------------------------------------------
// Tiled fp32 SGEMM: C[M,N] = act(A[M,K] @ B[K,N] + bias)
// BM=BN=128, BK=16, 256 threads, 8x8 per thread.
// Assumes M%128==0, K%16==0, N%4==0 (all true here). N guarded (N=64 case).
template<bool RELU>
__global__ __launch_bounds__(256)
void sgemm(const float* __restrict__ A, const float* __restrict__ B,
           const float* __restrict__ bias, float* __restrict__ C,
           int M, int N, int K)
{
    __shared__ float As[16][128];
    __shared__ float Bs[16][128];
    const int tid  = threadIdx.x;
    const int row0 = blockIdx.y * 128;
    const int col0 = blockIdx.x * 128;
    const int ty = tid >> 4;   // 0..15
    const int tx = tid & 15;   // 0..15

    float acc[8][8];
#pragma unroll
    for (int i = 0; i < 8; i++)
#pragma unroll
        for (int j = 0; j < 8; j++) acc[i][j] = 0.f;

    for (int k0 = 0; k0 < K; k0 += 16) {
        // load A tile (128 rows x 16 k), store transposed As[k][m]
#pragma unroll
        for (int i = 0; i < 2; i++) {
            int f4 = tid + 256 * i;          // 0..511
            int r  = f4 >> 2;                // 0..127
            int kk = (f4 & 3) << 2;          // 0,4,8,12
            const float4 v = *reinterpret_cast<const float4*>(
                A + (size_t)(row0 + r) * K + k0 + kk);
            As[kk + 0][r] = v.x; As[kk + 1][r] = v.y;
            As[kk + 2][r] = v.z; As[kk + 3][r] = v.w;
        }
        // load B tile (16 k x 128 n)
#pragma unroll
        for (int i = 0; i < 2; i++) {
            int f4 = tid + 256 * i;
            int r  = f4 >> 5;                // 0..15
            int cc = (f4 & 31) << 2;         // 0..124
            float4 v = make_float4(0.f, 0.f, 0.f, 0.f);
            if (col0 + cc < N)
                v = *reinterpret_cast<const float4*>(
                    B + (size_t)(k0 + r) * N + col0 + cc);
            *reinterpret_cast<float4*>(&Bs[r][cc]) = v;
        }
        __syncthreads();
#pragma unroll
        for (int kk = 0; kk < 16; kk++) {
            float a[8], b[8];
#pragma unroll
            for (int i = 0; i < 8; i++) a[i] = As[kk][ty * 8 + i];
#pragma unroll
            for (int j = 0; j < 8; j++) b[j] = Bs[kk][tx * 8 + j];
#pragma unroll
            for (int i = 0; i < 8; i++)
#pragma unroll
                for (int j = 0; j < 8; j++)
                    acc[i][j] = fmaf(a[i], b[j], acc[i][j]);
        }
        __syncthreads();
    }
#pragma unroll
    for (int i = 0; i < 8; i++) {
        const size_t r = (size_t)(row0 + ty * 8 + i);
#pragma unroll
        for (int j = 0; j < 8; j += 4) {
            int c = col0 + tx * 8 + j;
            if (c < N) {
                float4 v;
                v.x = acc[i][j + 0] + bias[c + 0];
                v.y = acc[i][j + 1] + bias[c + 1];
                v.z = acc[i][j + 2] + bias[c + 2];
                v.w = acc[i][j + 3] + bias[c + 3];
                if (RELU) {
                    v.x = fmaxf(v.x, 0.f); v.y = fmaxf(v.y, 0.f);
                    v.z = fmaxf(v.z, 0.f); v.w = fmaxf(v.w, 0.f);
                }
                *reinterpret_cast<float4*>(C + r * N + c) = v;
            }
        }
    }
}

// -------------------------------------------------------------------------
__device__ double block_reduce_sum(double v) {
    __shared__ double sh[32];
    int lane = threadIdx.x & 31;
    int w    = threadIdx.x >> 5;
#pragma unroll
    for (int o = 16; o > 0; o >>= 1) v += __shfl_down_sync(0xffffffffu, v, o);
    if (lane == 0) sh[w] = v;
    __syncthreads();
    int nw = (blockDim.x + 31) >> 5;
    v = (threadIdx.x < nw) ? sh[threadIdx.x] : 0.0;
    if (w == 0) {
#pragma unroll
        for (int o = 16; o > 0; o >>= 1) v += __shfl_down_sync(0xffffffffu, v, o);
    }
    return v;
}

// -------------------------------------------------------------------------
// VQ: argmin over 256 codes, emit idx (as float) + x_q, counts, vq partial sum
__global__ __launch_bounds__(128)
void vq_kernel(const float* __restrict__ cb, float* __restrict__ out_idx,
               float* __restrict__ out_xq)
{
    __shared__ float scc[N_CODE];  // ||codebook_c||^2
    int tid = threadIdx.x;
    for (int c = tid; c < N_CODE; c += 128) {
        float s = 0.f;
#pragma unroll
        for (int e = 0; e < D_E; e++) { float w = cb[c * D_E + e]; s = fmaf(w, w, s); }
        scc[c] = s;
    }
    __syncthreads();

    int row = blockIdx.x * 128 + tid;
    float zr[D_E];
    float zz = 0.f;
#pragma unroll
    for (int e = 0; e < D_E; e++) {
        zr[e] = g_z[(size_t)row * D_E + e];
        zz = fmaf(zr[e], zr[e], zz);
    }
    float best = 3.4e38f; int bi = 0;
    for (int c = 0; c < N_CODE; c++) {
        float dot = 0.f;
#pragma unroll
        for (int e = 0; e < D_E; e++) dot = fmaf(zr[e], __ldg(cb + c * D_E + e), dot);
        float d = zz - 2.f * dot + scc[c];
        if (d < best) { best = d; bi = c; }
    }
    g_idx[row]   = bi;
    out_idx[row] = (float)bi;
    float vq = 0.f;
#pragma unroll
    for (int e = 0; e < D_E; e++) {
        float xq = __ldg(cb + bi * D_E + e);
        out_xq[(size_t)row * D_E + e] = xq;   // x_q_st output (unaligned region: scalar)
        g_xq  [(size_t)row * D_E + e] = xq;   // aligned copy for decoder GEMM
        float df = xq - zr[e];
        vq = fmaf(df, df, vq);
    }
    atomicAdd(&g_cnt[bi], 1);
    double t = block_reduce_sum((double)vq);
    if (tid == 0) atomicAdd(&g_acc[0], t);
}

// -------------------------------------------------------------------------
__global__ __launch_bounds__(256)
void cos_kernel(const float* __restrict__ qdw) {
    int row = blockIdx.x * 256 + threadIdx.x;
    float dzq = 0.f, nz = 0.f, nq = 0.f;
#pragma unroll
    for (int e = 0; e < D_E; e++) {
        float zv = g_z [(size_t)row * D_E + e];
        float qv = g_qz[(size_t)row * D_E + e];
        dzq = fmaf(zv, qv, dzq);
        nz  = fmaf(zv, zv, nz);
        nq  = fmaf(qv, qv, nq);
    }
    float cosv = dzq / fmaxf(sqrtf(nz) * sqrtf(nq), 1e-8f);
    double v = (double)(qdw[row] * cosv);
    double t = block_reduce_sum(v);
    if (threadIdx.x == 0) atomicAdd(&g_acc[1], t);
}

// -------------------------------------------------------------------------
__global__ __launch_bounds__(256)
void trip_kernel(const int* __restrict__ tr) {
    int t = blockIdx.x * 256 + threadIdx.x;
    double v = 0.0;
    if (t < N_TRIP) {
        int a = tr[3 * t], p = tr[3 * t + 1], n = tr[3 * t + 2];
        float sp = 0.f, sn = 0.f;
#pragma unroll
        for (int e = 0; e < D_E; e++) {
            float av = g_z[(size_t)a * D_E + e];
            float d1 = av - g_z[(size_t)p * D_E + e]; sp = fmaf(d1, d1, sp);
            float d2 = av - g_z[(size_t)n * D_E + e]; sn = fmaf(d2, d2, sn);
        }
        float dp = sqrtf(sp + 1e-12f), dn = sqrtf(sn + 1e-12f);
        v = (double)fmaxf(dp - dn + 0.2f, 0.f);
    }
    double s = block_reduce_sum(v);
    if (threadIdx.x == 0) atomicAdd(&g_acc[2], s);
}

// -------------------------------------------------------------------------
// Contrastive shortcut: xn rows are the 256 normalized codebook rows, so
// sim takes only 256x256 values G = (cbn @ cbn.T)/TEMP and
// logsumexp(sim[k,:]) = m + log(sum_c counts[c] * exp(G[ca,c]-m)). Exact.
__global__ __launch_bounds__(256)
void code_stats(const float* __restrict__ cb) {
    int c = threadIdx.x;
    float myrow[D_E];
    float nrm = 0.f;
#pragma unroll
    for (int e = 0; e < D_E; e++) {
        myrow[e] = cb[c * D_E + e];
        nrm = fmaf(myrow[e], myrow[e], nrm);
    }
    nrm = fmaxf(sqrtf(nrm), 1e-12f);
#pragma unroll
    for (int e = 0; e < D_E; e++) { myrow[e] /= nrm; g_cbn[c * D_E + e] = myrow[e]; }
    __syncthreads();

    float m = -3.4e38f;
    for (int c2 = 0; c2 < N_CODE; c2++) {
        float dot = 0.f;
#pragma unroll
        for (int e = 0; e < D_E; e++) dot = fmaf(myrow[e], g_cbn[c2 * D_E + e], dot);
        float g = dot * 10.f;   // / TEMP (=0.1)
        g_G[c * N_CODE + c2] = g;
        if (g_cnt[c2] > 0 && g > m) m = g;
    }
    double s = 0.0;
    for (int c2 = 0; c2 < N_CODE; c2++) {
        int cnt = g_cnt[c2];
        if (cnt > 0) s += (double)cnt * (double)expf(g_G[c * N_CODE + c2] - m);
    }
    g_lse[c] = m + (float)log(s);
}

__global__ __launch_bounds__(256)
void pair_kernel(const int* __restrict__ pr) {
    int k = blockIdx.x * 256 + threadIdx.x;
    double v = 0.0;
    if (k < N_PAIR) {
        int ca = g_idx[pr[2 * k]];
        int cb2 = g_idx[pr[2 * k + 1]];
        v = (double)(g_lse[ca] - g_G[ca * N_CODE + cb2]);
    }
    double s = block_reduce_sum(v);
    if (threadIdx.x == 0) atomicAdd(&g_acc[3], s);
}

// -------------------------------------------------------------------------
__global__ void finalize_kernel(float* __restrict__ out) {
    out[VQ_OFF]    = (float)(g_acc[0] * 1.001 / ((double)N_ROWS * D_E));
    out[OUTER_OFF] = (float)(g_acc[3] / (double)N_PAIR);
    out[TRIP_OFF]  = (float)(g_acc[2] / (double)N_TRIP);
    out[QD_OFF]    = (float)(1.0 - g_acc[1] / (double)N_ROWS);
}

// -------------------------------------------------------------------------
extern "C" void kernel_launch(void* const* d_in, const int* in_sizes, int n_in,
                              void* d_out, int out_size)
{
    const float* x    = (const float*)d_in[0];
    const float* qe   = (const float*)d_in[1];
    const float* qdw  = (const float*)d_in[2];
    const int*   prs  = (const int*)  d_in[3];
    const int*   trs  = (const int*)  d_in[4];
    const float* ew0  = (const float*)d_in[5];
    const float* eb0  = (const float*)d_in[6];
    const float* ew1  = (const float*)d_in[7];
    const float* eb1  = (const float*)d_in[8];
    const float* ew2  = (const float*)d_in[9];
    const float* eb2  = (const float*)d_in[10];
    const float* dw0  = (const float*)d_in[11];
    const float* db0  = (const float*)d_in[12];
    const float* dw1  = (const float*)d_in[13];
    const float* db1  = (const float*)d_in[14];
    const float* dw2  = (const float*)d_in[15];
    const float* db2  = (const float*)d_in[16];
    const float* cb   = (const float*)d_in[17];
    float* out = (float*)d_out;

    float *h1, *h2, *z, *qz, *xq;
    cudaGetSymbolAddress((void**)&h1, g_h1);
    cudaGetSymbolAddress((void**)&h2, g_h2);
    cudaGetSymbolAddress((void**)&z,  g_z);
    cudaGetSymbolAddress((void**)&qz, g_qz);
    cudaGetSymbolAddress((void**)&xq, g_xq);

    init_kernel<<<1, 256>>>();

    // encoder(x) -> z
    sgemm<true ><<<dim3(16, 256), 256>>>(x,  ew0, eb0, h1, N_ROWS, D_H1, D_IN);
    sgemm<true ><<<dim3( 8, 256), 256>>>(h1, ew1, eb1, h2, N_ROWS, D_H2, D_H1);
    sgemm<false><<<dim3( 1, 256), 256>>>(h2, ew2, eb2, z,  N_ROWS, D_E,  D_H2);
    // encoder(q_embs) -> qz
    sgemm<true ><<<dim3(16, 256), 256>>>(qe, ew0, eb0, h1, N_ROWS, D_H1, D_IN);
    sgemm<true ><<<dim3( 8, 256), 256>>>(h1, ew1, eb1, h2, N_ROWS, D_H2, D_H1);
    sgemm<false><<<dim3( 1, 256), 256>>>(h2, ew2, eb2, qz, N_ROWS, D_E,  D_H2);

    // VQ + losses
    vq_kernel <<<256, 128>>>(cb, out + IDX_OFF, out + XQ_OFF);
    cos_kernel<<<128, 256>>>(qdw);
    trip_kernel<<<32, 256>>>(trs);
    code_stats<<<1, 256>>>(cb);
    pair_kernel<<<16, 256>>>(prs);

    // decoder(x_q) -> out
    sgemm<true ><<<dim3( 8, 256), 256>>>(xq, dw0, db0, h2, N_ROWS, D_H2, D_E);
    sgemm<true ><<<dim3(16, 256), 256>>>(h2, dw1, db1, h1, N_ROWS, D_H1, D_H2);
    sgemm<false><<<dim3( 6, 256), 256>>>(h1, dw2, db2, out, N_ROWS, D_IN, D_H1);

    finalize_kernel<<<1, 1>>>(out);
}

// round 4
// speedup vs baseline: 2.4414x; 2.4414x over previous
#include <cuda_runtime.h>
#include <cuda_bf16.h>
#include <math.h>
#include <stdint.h>

#define N_ROWS 32768
#define M_BOTH 65536
#define D_IN   768
#define D_H1   2048
#define D_H2   1024
#define D_E    64
#define N_CODE 256
#define N_PAIR 4096
#define N_TRIP 8192

#define VQ_OFF    25165824
#define IDX_OFF   25165825
#define XQ_OFF    25198593
#define OUTER_OFF 27295745
#define TRIP_OFF  27295746
#define QD_OFF    27295747

#define FLAG_EPS 1e-4f

// ---------------- scratch (device globals) ----------------
#define W0_OFF 0
#define W1_OFF 1572864
#define W2_OFF 3670016
#define W3_OFF 3735552
#define W4_OFF 3801088
#define W5_OFF 5898240
#define W_TOT  7471104
__device__ __align__(16) __nv_bfloat16 g_wh[W_TOT];
__device__ __align__(16) __nv_bfloat16 g_wl[W_TOT];

#define ACT_ELEMS ((size_t)M_BOTH * 2048)
__device__ __align__(16) __nv_bfloat16 g_a0h[ACT_ELEMS];
__device__ __align__(16) __nv_bfloat16 g_a0l[ACT_ELEMS];
__device__ __align__(16) __nv_bfloat16 g_a1h[ACT_ELEMS];  // also overlaid as fp32 rep1
__device__ __align__(16) __nv_bfloat16 g_a1l[ACT_ELEMS];  // also overlaid as fp32 rep2

__device__ float g_z [(size_t)M_BOTH * D_E];   // z (rows 0..32767) | qz (rows 32768..)
__device__ float g_zg[(size_t)N_ROWS * D_E];   // exact z for flagged rows (compact)
__device__ float g_cbn[N_CODE * D_E];
__device__ float g_G  [N_CODE * N_CODE];
__device__ float g_lse[N_CODE];
__device__ int   g_idx[N_ROWS];
__device__ int   g_cnt[N_CODE];
__device__ int   g_rowlist[N_ROWS];
__device__ int   g_nflag;
__device__ double g_acc[4];

// ---------------- helpers ----------------
__device__ __forceinline__ uint32_t smem_u32(const void* p) {
    uint32_t a;
    asm("{ .reg .u64 t; cvta.to.shared.u64 t, %1; cvt.u32.u64 %0, t; }" : "=r"(a) : "l"(p));
    return a;
}
#define LDSM4(r, a) \
    asm volatile("ldmatrix.sync.aligned.m8n8.x4.shared.b16 {%0,%1,%2,%3}, [%4];" \
        : "=r"((r)[0]), "=r"((r)[1]), "=r"((r)[2]), "=r"((r)[3]) : "r"(a))
#define MMA16816(d, a, b) \
    asm volatile("mma.sync.aligned.m16n8k16.row.col.f32.bf16.bf16.f32 " \
        "{%0,%1,%2,%3}, {%4,%5,%6,%7}, {%8,%9}, {%0,%1,%2,%3};" \
        : "+f"((d)[0]), "+f"((d)[1]), "+f"((d)[2]), "+f"((d)[3]) \
        : "r"((a)[0]), "r"((a)[1]), "r"((a)[2]), "r"((a)[3]), "r"((b)[0]), "r"((b)[1]))
#define CP_ASYNC16(sa, ga) \
    asm volatile("cp.async.cg.shared.global [%0], [%1], 16;" :: "r"(sa), "l"(ga))

// ---------------- prep kernels ----------------
__global__ void split_kernel(const float* __restrict__ src,
                             __nv_bfloat16* __restrict__ hi,
                             __nv_bfloat16* __restrict__ lo, size_t n) {
    for (size_t i = (size_t)blockIdx.x * blockDim.x + threadIdx.x; i < n;
         i += (size_t)gridDim.x * blockDim.x) {
        float v = src[i];
        __nv_bfloat16 h = __float2bfloat16(v);
        hi[i] = h;
        lo[i] = __float2bfloat16(v - __bfloat162float(h));
    }
}

__global__ __launch_bounds__(256)
void wprep_kernel(const float* __restrict__ W,
                  __nv_bfloat16* __restrict__ hi,
                  __nv_bfloat16* __restrict__ lo, int K, int N) {
    __shared__ float t[32][33];
    int kb = blockIdx.y * 32, nb = blockIdx.x * 32;
    int tx = threadIdx.x & 31, ty = threadIdx.x >> 5;
#pragma unroll
    for (int j = 0; j < 32; j += 8)
        t[ty + j][tx] = W[(size_t)(kb + ty + j) * N + nb + tx];
    __syncthreads();
#pragma unroll
    for (int j = 0; j < 32; j += 8) {
        float v = t[tx][ty + j];
        size_t o = (size_t)(nb + ty + j) * K + kb + tx;
        __nv_bfloat16 h = __float2bfloat16(v);
        hi[o] = h;
        lo[o] = __float2bfloat16(v - __bfloat162float(h));
    }
}

// ---------------- bf16 3-term mma GEMM ----------------
template<int BN, bool RELU, int OMODE>
__global__ __launch_bounds__(256, 1)
void gemm_mma(const __nv_bfloat16* __restrict__ Ahi, const __nv_bfloat16* __restrict__ Alo,
              const __nv_bfloat16* __restrict__ Bhi, const __nv_bfloat16* __restrict__ Blo,
              const float* __restrict__ bias,
              float* __restrict__ Of,
              __nv_bfloat16* __restrict__ Ohi, __nv_bfloat16* __restrict__ Olo,
              int Nn, int K)
{
    constexpr int WARPS_M = (BN == 128) ? 2 : 4;
    constexpr int WARPS_N = 8 / WARPS_M;
    constexpr int WM = 128 / WARPS_M;
    constexpr int WN = BN / WARPS_N;
    constexpr int MT = WM / 16;
    constexpr int NT = WN / 8;
    constexpr int ROWS = 256 + 2 * BN;
    constexpr int PITCH = 80;
    constexpr int STAGE = ROWS * PITCH;
    constexpr int CH = ROWS * 4;

    extern __shared__ __align__(16) char sm[];
    const int tid  = threadIdx.x;
    const int lane = tid & 31, wid = tid >> 5;
    const int wm = wid / WARPS_N, wn = wid % WARPS_N;
    const int row0 = blockIdx.y * 128;
    const int col0 = blockIdx.x * BN;
    const uint32_t sb = smem_u32(sm);

    const uint32_t aoff = ((lane & 7) + ((lane >> 3) & 1) * 8) * PITCH + ((lane >> 4) << 4);
    const uint32_t boff = ((lane & 7) + ((lane >> 4) & 1) * 8) * PITCH + (((lane >> 3) & 1) << 4);

    const int nk = K >> 5;

    auto load_stage = [&](int i) {
        uint32_t sbase = sb + (i % 3) * STAGE;
        int k0 = i << 5;
#pragma unroll
        for (int c = tid; c < CH; c += 256) {
            int r = c >> 2, ch = c & 3;
            const __nv_bfloat16* g;
            if (r < 128)            g = Ahi + (size_t)(row0 + r) * K;
            else if (r < 256)       g = Alo + (size_t)(row0 + r - 128) * K;
            else if (r < 256 + BN)  g = Bhi + (size_t)(col0 + r - 256) * K;
            else                    g = Blo + (size_t)(col0 + r - 256 - BN) * K;
            CP_ASYNC16(sbase + r * PITCH + ch * 16, g + k0 + ch * 8);
        }
        asm volatile("cp.async.commit_group;" ::: "memory");
    };

    float acc[MT][NT][4];
#pragma unroll
    for (int mi = 0; mi < MT; mi++)
#pragma unroll
        for (int ni = 0; ni < NT; ni++)
#pragma unroll
            for (int q = 0; q < 4; q++) acc[mi][ni][q] = 0.f;

    load_stage(0);
    load_stage(1);

    for (int i = 0; i < nk; i++) {
        if (i + 1 < nk) asm volatile("cp.async.wait_group 1;" ::: "memory");
        else            asm volatile("cp.async.wait_group 0;" ::: "memory");
        __syncthreads();
        if (i + 2 < nk) load_stage(i + 2);

        uint32_t sA = sb + (i % 3) * STAGE;
        uint32_t sB = sA + 256 * PITCH;
#pragma unroll
        for (int ks = 0; ks < 2; ks++) {
            uint32_t kofs = ks * 32;
            uint32_t ah[MT][4], al[MT][4], bh[NT][2], bl[NT][2];
#pragma unroll
            for (int mi = 0; mi < MT; mi++) {
                uint32_t base = sA + (uint32_t)(wm * WM + mi * 16) * PITCH + aoff + kofs;
                LDSM4(ah[mi], base);
                LDSM4(al[mi], base + 128 * PITCH);
            }
#pragma unroll
            for (int np = 0; np < NT / 2; np++) {
                uint32_t base = sB + (uint32_t)(wn * WN + np * 16) * PITCH + boff + kofs;
                uint32_t r[4];
                LDSM4(r, base);
                bh[2 * np][0] = r[0]; bh[2 * np][1] = r[1];
                bh[2 * np + 1][0] = r[2]; bh[2 * np + 1][1] = r[3];
                LDSM4(r, base + BN * PITCH);
                bl[2 * np][0] = r[0]; bl[2 * np][1] = r[1];
                bl[2 * np + 1][0] = r[2]; bl[2 * np + 1][1] = r[3];
            }
#pragma unroll
            for (int mi = 0; mi < MT; mi++)
#pragma unroll
                for (int ni = 0; ni < NT; ni++) MMA16816(acc[mi][ni], ah[mi], bh[ni]);
#pragma unroll
            for (int mi = 0; mi < MT; mi++)
#pragma unroll
                for (int ni = 0; ni < NT; ni++) MMA16816(acc[mi][ni], al[mi], bh[ni]);
#pragma unroll
            for (int mi = 0; mi < MT; mi++)
#pragma unroll
                for (int ni = 0; ni < NT; ni++) MMA16816(acc[mi][ni], ah[mi], bl[ni]);
        }
    }

#pragma unroll
    for (int mi = 0; mi < MT; mi++) {
        int rbase = row0 + wm * WM + mi * 16 + (lane >> 2);
#pragma unroll
        for (int ni = 0; ni < NT; ni++) {
            int c = col0 + wn * WN + ni * 8 + (lane & 3) * 2;
            float b0 = __ldg(&bias[c]), b1 = __ldg(&bias[c + 1]);
#pragma unroll
            for (int h = 0; h < 2; h++) {
                float v0 = acc[mi][ni][2 * h]     + b0;
                float v1 = acc[mi][ni][2 * h + 1] + b1;
                if (RELU) { v0 = fmaxf(v0, 0.f); v1 = fmaxf(v1, 0.f); }
                size_t o = (size_t)(rbase + 8 * h) * Nn + c;
                if (OMODE == 0) {
                    *reinterpret_cast<float2*>(Of + o) = make_float2(v0, v1);
                } else {
                    __nv_bfloat162 hh;
                    hh.x = __float2bfloat16(v0);
                    hh.y = __float2bfloat16(v1);
                    *reinterpret_cast<__nv_bfloat162*>(Ohi + o) = hh;
                    __nv_bfloat162 ll;
                    ll.x = __float2bfloat16(v0 - __bfloat162float(hh.x));
                    ll.y = __float2bfloat16(v1 - __bfloat162float(hh.y));
                    *reinterpret_cast<__nv_bfloat162*>(Olo + o) = ll;
                }
            }
        }
    }
}

#define SMEM_BN128 (3 * (256 + 256) * 80)
#define SMEM_BN64  (3 * (256 + 128) * 80)

// ---------------- fp32 SGEMM for repair path (dynamic M via nf_ptr) ----------------
template<bool RELU>
__global__ __launch_bounds__(256)
void sgemm_f32(const float* __restrict__ A, const float* __restrict__ B,
               const float* __restrict__ bias, float* __restrict__ C,
               const int* __restrict__ rowmap, const int* __restrict__ nf_ptr,
               int N, int K)
{
    const int nf = *nf_ptr;
    const int row0 = blockIdx.y * 128;
    if (row0 >= nf) return;

    __shared__ float As[16][128];
    __shared__ float Bs[16][128];
    const int tid  = threadIdx.x;
    const int col0 = blockIdx.x * 128;
    const int ty = tid >> 4;
    const int tx = tid & 15;

    float acc[8][8];
#pragma unroll
    for (int i = 0; i < 8; i++)
#pragma unroll
        for (int j = 0; j < 8; j++) acc[i][j] = 0.f;

    for (int k0 = 0; k0 < K; k0 += 16) {
#pragma unroll
        for (int i = 0; i < 2; i++) {
            int f4 = tid + 256 * i;
            int r  = f4 >> 2;
            int kk = (f4 & 3) << 2;
            int rr = row0 + r;
            if (rr >= nf) rr = nf - 1;
            int arow = rowmap ? rowmap[rr] : rr;
            const float4 v = *reinterpret_cast<const float4*>(
                A + (size_t)arow * K + k0 + kk);
            As[kk + 0][r] = v.x; As[kk + 1][r] = v.y;
            As[kk + 2][r] = v.z; As[kk + 3][r] = v.w;
        }
#pragma unroll
        for (int i = 0; i < 2; i++) {
            int f4 = tid + 256 * i;
            int r  = f4 >> 5;
            int cc = (f4 & 31) << 2;
            float4 v = make_float4(0.f, 0.f, 0.f, 0.f);
            if (col0 + cc < N)
                v = *reinterpret_cast<const float4*>(B + (size_t)(k0 + r) * N + col0 + cc);
            *reinterpret_cast<float4*>(&Bs[r][cc]) = v;
        }
        __syncthreads();
#pragma unroll
        for (int kk = 0; kk < 16; kk++) {
            float a[8], b[8];
#pragma unroll
            for (int i = 0; i < 8; i++) a[i] = As[kk][ty * 8 + i];
#pragma unroll
            for (int j = 0; j < 8; j++) b[j] = Bs[kk][tx * 8 + j];
#pragma unroll
            for (int i = 0; i < 8; i++)
#pragma unroll
                for (int j = 0; j < 8; j++)
                    acc[i][j] = fmaf(a[i], b[j], acc[i][j]);
        }
        __syncthreads();
    }
#pragma unroll
    for (int i = 0; i < 8; i++) {
        const size_t r = (size_t)(row0 + ty * 8 + i);
#pragma unroll
        for (int j = 0; j < 8; j += 4) {
            int c = col0 + tx * 8 + j;
            if (c < N) {
                float4 v;
                v.x = acc[i][j + 0] + bias[c + 0];
                v.y = acc[i][j + 1] + bias[c + 1];
                v.z = acc[i][j + 2] + bias[c + 2];
                v.w = acc[i][j + 3] + bias[c + 3];
                if (RELU) {
                    v.x = fmaxf(v.x, 0.f); v.y = fmaxf(v.y, 0.f);
                    v.z = fmaxf(v.z, 0.f); v.w = fmaxf(v.w, 0.f);
                }
                *reinterpret_cast<float4*>(C + r * N + c) = v;
            }
        }
    }
}

// ---------------- reduction helper ----------------
__device__ double block_reduce_sum(double v) {
    __shared__ double sh[32];
    int lane = threadIdx.x & 31, w = threadIdx.x >> 5;
#pragma unroll
    for (int o = 16; o > 0; o >>= 1) v += __shfl_down_sync(0xffffffffu, v, o);
    if (lane == 0) sh[w] = v;
    __syncthreads();
    int nw = (blockDim.x + 31) >> 5;
    v = (threadIdx.x < nw) ? sh[threadIdx.x] : 0.0;
    if (w == 0)
#pragma unroll
        for (int o = 16; o > 0; o >>= 1) v += __shfl_down_sync(0xffffffffu, v, o);
    return v;
}

// ---------------- small kernels ----------------
__global__ void init_kernel() {
    int t = threadIdx.x;
    if (t < 4) g_acc[t] = 0.0;
    if (t < N_CODE) g_cnt[t] = 0;
    if (t == 0) g_nflag = 0;
}

// VQ pass 1: approx argmin; flag rows with small top-2 margin for fp32 repair.
__global__ __launch_bounds__(128)
void vq_kernel(const float* __restrict__ cb, float* __restrict__ out_idx,
               float* __restrict__ out_xq)
{
    __shared__ float scc[N_CODE];
    int tid = threadIdx.x;
    for (int c = tid; c < N_CODE; c += 128) {
        float s = 0.f;
#pragma unroll
        for (int e = 0; e < D_E; e++) { float w = cb[c * D_E + e]; s = fmaf(w, w, s); }
        scc[c] = s;
    }
    __syncthreads();

    float ccmax = 0.f;
    for (int c = 0; c < N_CODE; c++) ccmax = fmaxf(ccmax, scc[c]);

    int row = blockIdx.x * 128 + tid;
    float zr[D_E];
    float zz = 0.f;
#pragma unroll
    for (int e = 0; e < D_E; e++) {
        zr[e] = g_z[(size_t)row * D_E + e];
        zz = fmaf(zr[e], zr[e], zz);
    }
    float best = 3.4e38f, sec = 3.4e38f; int bi = 0;
    for (int c = 0; c < N_CODE; c++) {
        float dot = 0.f;
#pragma unroll
        for (int e = 0; e < D_E; e++) dot = fmaf(zr[e], __ldg(cb + c * D_E + e), dot);
        float d = zz - 2.f * dot + scc[c];
        if (d < best) { sec = best; best = d; bi = c; }
        else if (d < sec) sec = d;
    }

    float nz = sqrtf(zz), cmax = sqrtf(ccmax);
    float thresh = FLAG_EPS * nz * (nz + cmax) + 1e-6f;
    bool flagged = (sec - best) < thresh;

    float vq = 0.f;
    if (flagged) {
        int pos = atomicAdd(&g_nflag, 1);
        g_rowlist[pos] = row;
    } else {
        g_idx[row]   = bi;
        out_idx[row] = (float)bi;
#pragma unroll
        for (int e = 0; e < D_E; e++) {
            float xq = __ldg(cb + bi * D_E + e);
            out_xq[(size_t)row * D_E + e] = xq;
            __nv_bfloat16 h = __float2bfloat16(xq);
            g_a0h[(size_t)row * D_E + e] = h;
            g_a0l[(size_t)row * D_E + e] = __float2bfloat16(xq - __bfloat162float(h));
            float df = xq - zr[e];
            vq = fmaf(df, df, vq);
        }
        atomicAdd(&g_cnt[bi], 1);
    }
    double t = block_reduce_sum((double)vq);
    if (tid == 0) atomicAdd(&g_acc[0], t);
}

// VQ pass 2: flagged rows — exact fp32 z (g_zg) -> exact argmin + all outputs.
__global__ __launch_bounds__(256)
void repair_kernel(const float* __restrict__ cb, float* __restrict__ out_idx,
                   float* __restrict__ out_xq)
{
    __shared__ float zrow[D_E];
    __shared__ float dsh[N_CODE];
    __shared__ int   rwin;
    int tid = threadIdx.x;
    int nf = g_nflag;
    for (int i = blockIdx.x; i < nf; i += gridDim.x) {
        int row = g_rowlist[i];
        if (tid < D_E) zrow[tid] = g_zg[(size_t)i * D_E + tid];
        __syncthreads();
        float zz = 0.f;
#pragma unroll
        for (int e = 0; e < D_E; e++) zz = fmaf(zrow[e], zrow[e], zz);
        {
            int c = tid;  // 256 threads = 256 codes
            float dot = 0.f, cc = 0.f;
#pragma unroll
            for (int e = 0; e < D_E; e++) {
                float w = __ldg(cb + c * D_E + e);
                dot = fmaf(zrow[e], w, dot);
                cc  = fmaf(w, w, cc);
            }
            dsh[c] = zz - 2.f * dot + cc;
        }
        __syncthreads();
        if (tid == 0) {
            float best = dsh[0]; int bi = 0;
            for (int c = 1; c < N_CODE; c++)
                if (dsh[c] < best) { best = dsh[c]; bi = c; }
            rwin = bi;
            g_idx[row] = bi;
            out_idx[row] = (float)bi;
            atomicAdd(&g_cnt[bi], 1);
        }
        __syncthreads();
        int bi = rwin;
        if (tid < D_E) {
            int e = tid;
            float zv = zrow[e];
            float xq = __ldg(cb + bi * D_E + e);
            out_xq[(size_t)row * D_E + e] = xq;
            __nv_bfloat16 h = __float2bfloat16(xq);
            g_a0h[(size_t)row * D_E + e] = h;
            g_a0l[(size_t)row * D_E + e] = __float2bfloat16(xq - __bfloat162float(h));
            g_z[(size_t)row * D_E + e] = zv;   // exact z for cos/trip
        }
        // vq contribution (thread 0, 64 elems: cheap)
        if (tid == 0) {
            float vq = 0.f;
#pragma unroll
            for (int e = 0; e < D_E; e++) {
                float df = __ldg(cb + bi * D_E + e) - zrow[e];
                vq = fmaf(df, df, vq);
            }
            atomicAdd(&g_acc[0], (double)vq);
        }
        __syncthreads();
    }
}

__global__ __launch_bounds__(256)
void cos_kernel(const float* __restrict__ qdw) {
    int row = blockIdx.x * 256 + threadIdx.x;
    const float* qz = g_z + (size_t)N_ROWS * D_E;
    float dzq = 0.f, nz = 0.f, nq = 0.f;
#pragma unroll
    for (int e = 0; e < D_E; e++) {
        float zv = g_z[(size_t)row * D_E + e];
        float qv = qz [(size_t)row * D_E + e];
        dzq = fmaf(zv, qv, dzq);
        nz  = fmaf(zv, zv, nz);
        nq  = fmaf(qv, qv, nq);
    }
    float cosv = dzq / fmaxf(sqrtf(nz) * sqrtf(nq), 1e-8f);
    double t = block_reduce_sum((double)(qdw[row] * cosv));
    if (threadIdx.x == 0) atomicAdd(&g_acc[1], t);
}

__global__ __launch_bounds__(256)
void trip_kernel(const int* __restrict__ tr) {
    int t = blockIdx.x * 256 + threadIdx.x;
    double v = 0.0;
    if (t < N_TRIP) {
        int a = tr[3 * t], p = tr[3 * t + 1], n = tr[3 * t + 2];
        float sp = 0.f, sn = 0.f;
#pragma unroll
        for (int e = 0; e < D_E; e++) {
            float av = g_z[(size_t)a * D_E + e];
            float d1 = av - g_z[(size_t)p * D_E + e]; sp = fmaf(d1, d1, sp);
            float d2 = av - g_z[(size_t)n * D_E + e]; sn = fmaf(d2, d2, sn);
        }
        v = (double)fmaxf(sqrtf(sp + 1e-12f) - sqrtf(sn + 1e-12f) + 0.2f, 0.f);
    }
    double s = block_reduce_sum(v);
    if (threadIdx.x == 0) atomicAdd(&g_acc[2], s);
}

// Exact contrastive shortcut: xn rows take 256 values (normalized codebook).
__global__ __launch_bounds__(256)
void code_stats(const float* __restrict__ cb) {
    int c = threadIdx.x;
    float myrow[D_E];
    float nrm = 0.f;
#pragma unroll
    for (int e = 0; e < D_E; e++) {
        myrow[e] = cb[c * D_E + e];
        nrm = fmaf(myrow[e], myrow[e], nrm);
    }
    nrm = fmaxf(sqrtf(nrm), 1e-12f);
#pragma unroll
    for (int e = 0; e < D_E; e++) { myrow[e] /= nrm; g_cbn[c * D_E + e] = myrow[e]; }
    __syncthreads();

    float m = -3.4e38f;
    for (int c2 = 0; c2 < N_CODE; c2++) {
        float dot = 0.f;
#pragma unroll
        for (int e = 0; e < D_E; e++) dot = fmaf(myrow[e], g_cbn[c2 * D_E + e], dot);
        float g = dot * 10.f;
        g_G[c * N_CODE + c2] = g;
        if (g_cnt[c2] > 0 && g > m) m = g;
    }
    double s = 0.0;
    for (int c2 = 0; c2 < N_CODE; c2++) {
        int cnt = g_cnt[c2];
        if (cnt > 0) s += (double)cnt * (double)expf(g_G[c * N_CODE + c2] - m);
    }
    g_lse[c] = m + (float)log(s);
}

__global__ __launch_bounds__(256)
void pair_kernel(const int* __restrict__ pr) {
    int k = blockIdx.x * 256 + threadIdx.x;
    double v = 0.0;
    if (k < N_PAIR) {
        int ca = g_idx[pr[2 * k]];
        int cb2 = g_idx[pr[2 * k + 1]];
        v = (double)(g_lse[ca] - g_G[ca * N_CODE + cb2]);
    }
    double s = block_reduce_sum(v);
    if (threadIdx.x == 0) atomicAdd(&g_acc[3], s);
}

__global__ void finalize_kernel(float* __restrict__ out) {
    out[VQ_OFF]    = (float)(g_acc[0] * 1.001 / ((double)N_ROWS * D_E));
    out[OUTER_OFF] = (float)(g_acc[3] / (double)N_PAIR);
    out[TRIP_OFF]  = (float)(g_acc[2] / (double)N_TRIP);
    out[QD_OFF]    = (float)(1.0 - g_acc[1] / (double)N_ROWS);
}

// ---------------- launch ----------------
extern "C" void kernel_launch(void* const* d_in, const int* in_sizes, int n_in,
                              void* d_out, int out_size)
{
    const float* x    = (const float*)d_in[0];
    const float* qe   = (const float*)d_in[1];
    const float* qdw  = (const float*)d_in[2];
    const int*   prs  = (const int*)  d_in[3];
    const int*   trs  = (const int*)  d_in[4];
    const float* ew0  = (const float*)d_in[5];
    const float* eb0  = (const float*)d_in[6];
    const float* ew1  = (const float*)d_in[7];
    const float* eb1  = (const float*)d_in[8];
    const float* ew2  = (const float*)d_in[9];
    const float* eb2  = (const float*)d_in[10];
    const float* dw0  = (const float*)d_in[11];
    const float* db0  = (const float*)d_in[12];
    const float* dw1  = (const float*)d_in[13];
    const float* db1  = (const float*)d_in[14];
    const float* dw2  = (const float*)d_in[15];
    const float* db2  = (const float*)d_in[16];
    const float* cb   = (const float*)d_in[17];
    float* out = (float*)d_out;

    cudaFuncSetAttribute(gemm_mma<128, true,  1>, cudaFuncAttributeMaxDynamicSharedMemorySize, SMEM_BN128);
    cudaFuncSetAttribute(gemm_mma<128, false, 0>, cudaFuncAttributeMaxDynamicSharedMemorySize, SMEM_BN128);
    cudaFuncSetAttribute(gemm_mma<64,  false, 0>, cudaFuncAttributeMaxDynamicSharedMemorySize, SMEM_BN64);

    __nv_bfloat16 *wh, *wl, *a0h, *a0l, *a1h, *a1l;
    float *z, *zg;
    int *rowlist, *nflag;
    cudaGetSymbolAddress((void**)&wh,  g_wh);
    cudaGetSymbolAddress((void**)&wl,  g_wl);
    cudaGetSymbolAddress((void**)&a0h, g_a0h);
    cudaGetSymbolAddress((void**)&a0l, g_a0l);
    cudaGetSymbolAddress((void**)&a1h, g_a1h);
    cudaGetSymbolAddress((void**)&a1l, g_a1l);
    cudaGetSymbolAddress((void**)&z,   g_z);
    cudaGetSymbolAddress((void**)&zg,  g_zg);
    cudaGetSymbolAddress((void**)&rowlist, g_rowlist);
    cudaGetSymbolAddress((void**)&nflag,   g_nflag);
    float* rep1 = (float*)a1h;   // overlay: dead between enc-L2 and dec-L1
    float* rep2 = (float*)a1l;

    init_kernel<<<1, 256>>>();

    wprep_kernel<<<dim3(D_H1 / 32, D_IN / 32), 256>>>(ew0, wh + W0_OFF, wl + W0_OFF, D_IN, D_H1);
    wprep_kernel<<<dim3(D_H2 / 32, D_H1 / 32), 256>>>(ew1, wh + W1_OFF, wl + W1_OFF, D_H1, D_H2);
    wprep_kernel<<<dim3(D_E  / 32, D_H2 / 32), 256>>>(ew2, wh + W2_OFF, wl + W2_OFF, D_H2, D_E);
    wprep_kernel<<<dim3(D_H2 / 32, D_E  / 32), 256>>>(dw0, wh + W3_OFF, wl + W3_OFF, D_E,  D_H2);
    wprep_kernel<<<dim3(D_H1 / 32, D_H2 / 32), 256>>>(dw1, wh + W4_OFF, wl + W4_OFF, D_H2, D_H1);
    wprep_kernel<<<dim3(D_IN / 32, D_H1 / 32), 256>>>(dw2, wh + W5_OFF, wl + W5_OFF, D_H1, D_IN);

    // ---- encoder over [x ; q_embs] (M = 65536) ----
    split_kernel<<<2048, 256>>>(x,  a0h, a0l, (size_t)N_ROWS * D_IN);
    split_kernel<<<2048, 256>>>(qe, a0h + (size_t)N_ROWS * D_IN, a0l + (size_t)N_ROWS * D_IN,
                                (size_t)N_ROWS * D_IN);
    gemm_mma<128, true,  1><<<dim3(16, 512), 256, SMEM_BN128>>>(a0h, a0l, wh + W0_OFF, wl + W0_OFF, eb0, nullptr, a1h, a1l, D_H1, D_IN);
    gemm_mma<128, true,  1><<<dim3( 8, 512), 256, SMEM_BN128>>>(a1h, a1l, wh + W1_OFF, wl + W1_OFF, eb1, nullptr, a0h, a0l, D_H2, D_H1);
    gemm_mma<64,  false, 0><<<dim3( 1, 512), 256, SMEM_BN64 >>>(a0h, a0l, wh + W2_OFF, wl + W2_OFF, eb2, z, nullptr, nullptr, D_E, D_H2);

    // ---- VQ pass 1 (flags risky rows) ----
    vq_kernel<<<256, 128>>>(cb, out + IDX_OFF, out + XQ_OFF);

    // ---- fp32 repair path for flagged rows ----
    sgemm_f32<true ><<<dim3(16, 256), 256>>>(x,    ew0, eb0, rep1, rowlist, nflag, D_H1, D_IN);
    sgemm_f32<true ><<<dim3( 8, 256), 256>>>(rep1, ew1, eb1, rep2, nullptr, nflag, D_H2, D_H1);
    sgemm_f32<false><<<dim3( 1, 256), 256>>>(rep2, ew2, eb2, zg,   nullptr, nflag, D_E,  D_H2);
    repair_kernel<<<512, 256>>>(cb, out + IDX_OFF, out + XQ_OFF);

    // ---- losses ----
    cos_kernel<<<128, 256>>>(qdw);
    trip_kernel<<<32, 256>>>(trs);
    code_stats<<<1, 256>>>(cb);
    pair_kernel<<<16, 256>>>(prs);

    // ---- decoder ----
    gemm_mma<128, true,  1><<<dim3( 8, 256), 256, SMEM_BN128>>>(a0h, a0l, wh + W3_OFF, wl + W3_OFF, db0, nullptr, a1h, a1l, D_H2, D_E);
    gemm_mma<128, true,  1><<<dim3(16, 256), 256, SMEM_BN128>>>(a1h, a1l, wh + W4_OFF, wl + W4_OFF, db1, nullptr, a0h, a0l, D_H1, D_H2);
    gemm_mma<128, false, 0><<<dim3( 6, 256), 256, SMEM_BN128>>>(a0h, a0l, wh + W5_OFF, wl + W5_OFF, db2, out, nullptr, nullptr, D_IN, D_H1);

    finalize_kernel<<<1, 1>>>(out);
}

// round 5
// speedup vs baseline: 3.4615x; 1.4178x over previous
#include <cuda_runtime.h>
#include <cuda_fp16.h>
#include <math.h>
#include <stdint.h>

#define N_ROWS 32768
#define D_IN   768
#define D_H1   2048
#define D_H2   1024
#define D_E    64
#define N_CODE 256
#define N_PAIR 4096
#define N_TRIP 8192

#define VQ_OFF    25165824
#define IDX_OFF   25165825
#define XQ_OFF    25198593
#define OUTER_OFF 27295745
#define TRIP_OFF  27295746
#define QD_OFF    27295747

#define FLAG_EPS 2e-5f

// ---------------- scratch (device globals) ----------------
// encoder weights only, [N,K] transposed, hi/lo fp16
#define W0_OFF 0          // enc_w0: N=2048,K=768
#define W1_OFF 1572864    // enc_w1: N=1024,K=2048
#define W2_OFF 3670016    // enc_w2: N=64,  K=1024
#define W_TOT  3735552
__device__ __align__(16) __half g_wh[W_TOT];
__device__ __align__(16) __half g_wl[W_TOT];

#define ACT_ELEMS ((size_t)N_ROWS * 2048)
__device__ __align__(16) __half g_a0h[ACT_ELEMS];
__device__ __align__(16) __half g_a0l[ACT_ELEMS];
__device__ __align__(16) __half g_a1h[ACT_ELEMS];
__device__ __align__(16) __half g_a1l[ACT_ELEMS];

__device__ float g_z [(size_t)N_ROWS * D_E];
__device__ float g_qz[(size_t)N_ROWS * D_E];
__device__ float g_zg[(size_t)N_ROWS * D_E];          // exact z for flagged rows
__device__ float g_rep1[(size_t)N_ROWS * D_H1];       // fp32 repair scratch
__device__ float g_rep2[(size_t)N_ROWS * D_H2];
__device__ float g_dec1[N_CODE * D_H2];
__device__ float g_dec2[N_CODE * D_H1];
__device__ float g_dec3[N_CODE * D_IN];
__device__ float g_cbn[N_CODE * D_E];
__device__ float g_G  [N_CODE * N_CODE];
__device__ float g_lse[N_CODE];
__device__ int   g_idx[N_ROWS];
__device__ int   g_cnt[N_CODE];
__device__ int   g_rowlist[N_ROWS];
__device__ int   g_nflag;
__device__ int   g_m256 = 256;
__device__ double g_acc[4];

// ---------------- helpers ----------------
__device__ __forceinline__ uint32_t smem_u32(const void* p) {
    uint32_t a;
    asm("{ .reg .u64 t; cvta.to.shared.u64 t, %1; cvt.u32.u64 %0, t; }" : "=r"(a) : "l"(p));
    return a;
}
#define LDSM4(r, a) \
    asm volatile("ldmatrix.sync.aligned.m8n8.x4.shared.b16 {%0,%1,%2,%3}, [%4];" \
        : "=r"((r)[0]), "=r"((r)[1]), "=r"((r)[2]), "=r"((r)[3]) : "r"(a))
#define MMA16816(d, a, b) \
    asm volatile("mma.sync.aligned.m16n8k16.row.col.f32.f16.f16.f32 " \
        "{%0,%1,%2,%3}, {%4,%5,%6,%7}, {%8,%9}, {%0,%1,%2,%3};" \
        : "+f"((d)[0]), "+f"((d)[1]), "+f"((d)[2]), "+f"((d)[3]) \
        : "r"((a)[0]), "r"((a)[1]), "r"((a)[2]), "r"((a)[3]), "r"((b)[0]), "r"((b)[1]))
#define CP_ASYNC16(sa, ga) \
    asm volatile("cp.async.cg.shared.global [%0], [%1], 16;" :: "r"(sa), "l"(ga))

// ---------------- prep kernels ----------------
__global__ void split_kernel(const float* __restrict__ src,
                             __half* __restrict__ hi,
                             __half* __restrict__ lo, size_t n) {
    for (size_t i = (size_t)blockIdx.x * blockDim.x + threadIdx.x; i < n;
         i += (size_t)gridDim.x * blockDim.x) {
        float v = src[i];
        __half h = __float2half(v);
        hi[i] = h;
        lo[i] = __float2half(v - __half2float(h));
    }
}

__global__ __launch_bounds__(256)
void wprep_kernel(const float* __restrict__ W,
                  __half* __restrict__ hi,
                  __half* __restrict__ lo, int K, int N) {
    __shared__ float t[32][33];
    int kb = blockIdx.y * 32, nb = blockIdx.x * 32;
    int tx = threadIdx.x & 31, ty = threadIdx.x >> 5;
#pragma unroll
    for (int j = 0; j < 32; j += 8)
        t[ty + j][tx] = W[(size_t)(kb + ty + j) * N + nb + tx];
    __syncthreads();
#pragma unroll
    for (int j = 0; j < 32; j += 8) {
        float v = t[tx][ty + j];
        size_t o = (size_t)(nb + ty + j) * K + kb + tx;
        __half h = __float2half(v);
        hi[o] = h;
        lo[o] = __float2half(v - __half2float(h));
    }
}

// ---------------- fp16 multi-term mma GEMM ----------------
// TERMS=3: AhBh + AlBh + AhBl.  TERMS=2: AhBh + AlBh (B-lo never loaded).
template<int BN, bool RELU, int OMODE, int TERMS>
__global__ __launch_bounds__(256, 1)
void gemm_mma(const __half* __restrict__ Ahi, const __half* __restrict__ Alo,
              const __half* __restrict__ Bhi, const __half* __restrict__ Blo,
              const float* __restrict__ bias,
              float* __restrict__ Of,
              __half* __restrict__ Ohi, __half* __restrict__ Olo,
              int Nn, int K)
{
    constexpr int WARPS_M = (BN == 128) ? 2 : 4;
    constexpr int WARPS_N = 8 / WARPS_M;
    constexpr int WM = 128 / WARPS_M;
    constexpr int WN = BN / WARPS_N;
    constexpr int MT = WM / 16;
    constexpr int NT = WN / 8;
    constexpr int ROWS = 256 + 2 * BN;
    constexpr int LROWS = (TERMS == 3) ? ROWS : (256 + BN);
    constexpr int PITCH = 80;
    constexpr int STAGE = ROWS * PITCH;
    constexpr int CH = LROWS * 4;

    extern __shared__ __align__(16) char sm[];
    const int tid  = threadIdx.x;
    const int lane = tid & 31, wid = tid >> 5;
    const int wm = wid / WARPS_N, wn = wid % WARPS_N;
    const int row0 = blockIdx.y * 128;
    const int col0 = blockIdx.x * BN;
    const uint32_t sb = smem_u32(sm);

    const uint32_t aoff = ((lane & 7) + ((lane >> 3) & 1) * 8) * PITCH + ((lane >> 4) << 4);
    const uint32_t boff = ((lane & 7) + ((lane >> 4) & 1) * 8) * PITCH + (((lane >> 3) & 1) << 4);

    const int nk = K >> 5;

    auto load_stage = [&](int i) {
        uint32_t sbase = sb + (i % 3) * STAGE;
        int k0 = i << 5;
#pragma unroll
        for (int c = tid; c < CH; c += 256) {
            int r = c >> 2, ch = c & 3;
            const __half* g;
            if (r < 128)            g = Ahi + (size_t)(row0 + r) * K;
            else if (r < 256)       g = Alo + (size_t)(row0 + r - 128) * K;
            else if (r < 256 + BN)  g = Bhi + (size_t)(col0 + r - 256) * K;
            else                    g = Blo + (size_t)(col0 + r - 256 - BN) * K;
            CP_ASYNC16(sbase + r * PITCH + ch * 16, g + k0 + ch * 8);
        }
        asm volatile("cp.async.commit_group;" ::: "memory");
    };

    float acc[MT][NT][4];
#pragma unroll
    for (int mi = 0; mi < MT; mi++)
#pragma unroll
        for (int ni = 0; ni < NT; ni++)
#pragma unroll
            for (int q = 0; q < 4; q++) acc[mi][ni][q] = 0.f;

    load_stage(0);
    load_stage(1);

    for (int i = 0; i < nk; i++) {
        if (i + 1 < nk) asm volatile("cp.async.wait_group 1;" ::: "memory");
        else            asm volatile("cp.async.wait_group 0;" ::: "memory");
        __syncthreads();
        if (i + 2 < nk) load_stage(i + 2);

        uint32_t sA = sb + (i % 3) * STAGE;
        uint32_t sB = sA + 256 * PITCH;
#pragma unroll
        for (int ks = 0; ks < 2; ks++) {
            uint32_t kofs = ks * 32;
            uint32_t ah[MT][4], al[MT][4], bh[NT][2], bl[NT][2];
#pragma unroll
            for (int mi = 0; mi < MT; mi++) {
                uint32_t base = sA + (uint32_t)(wm * WM + mi * 16) * PITCH + aoff + kofs;
                LDSM4(ah[mi], base);
                LDSM4(al[mi], base + 128 * PITCH);
            }
#pragma unroll
            for (int np = 0; np < NT / 2; np++) {
                uint32_t base = sB + (uint32_t)(wn * WN + np * 16) * PITCH + boff + kofs;
                uint32_t r[4];
                LDSM4(r, base);
                bh[2 * np][0] = r[0]; bh[2 * np][1] = r[1];
                bh[2 * np + 1][0] = r[2]; bh[2 * np + 1][1] = r[3];
                if (TERMS == 3) {
                    LDSM4(r, base + BN * PITCH);
                    bl[2 * np][0] = r[0]; bl[2 * np][1] = r[1];
                    bl[2 * np + 1][0] = r[2]; bl[2 * np + 1][1] = r[3];
                }
            }
#pragma unroll
            for (int mi = 0; mi < MT; mi++)
#pragma unroll
                for (int ni = 0; ni < NT; ni++) MMA16816(acc[mi][ni], ah[mi], bh[ni]);
#pragma unroll
            for (int mi = 0; mi < MT; mi++)
#pragma unroll
                for (int ni = 0; ni < NT; ni++) MMA16816(acc[mi][ni], al[mi], bh[ni]);
            if (TERMS == 3) {
#pragma unroll
                for (int mi = 0; mi < MT; mi++)
#pragma unroll
                    for (int ni = 0; ni < NT; ni++) MMA16816(acc[mi][ni], ah[mi], bl[ni]);
            }
        }
    }

#pragma unroll
    for (int mi = 0; mi < MT; mi++) {
        int rbase = row0 + wm * WM + mi * 16 + (lane >> 2);
#pragma unroll
        for (int ni = 0; ni < NT; ni++) {
            int c = col0 + wn * WN + ni * 8 + (lane & 3) * 2;
            float b0 = __ldg(&bias[c]), b1 = __ldg(&bias[c + 1]);
#pragma unroll
            for (int h = 0; h < 2; h++) {
                float v0 = acc[mi][ni][2 * h]     + b0;
                float v1 = acc[mi][ni][2 * h + 1] + b1;
                if (RELU) { v0 = fmaxf(v0, 0.f); v1 = fmaxf(v1, 0.f); }
                size_t o = (size_t)(rbase + 8 * h) * Nn + c;
                if (OMODE == 0) {
                    *reinterpret_cast<float2*>(Of + o) = make_float2(v0, v1);
                } else {
                    __half2 hh;
                    hh.x = __float2half(v0);
                    hh.y = __float2half(v1);
                    *reinterpret_cast<__half2*>(Ohi + o) = hh;
                    __half2 ll;
                    ll.x = __float2half(v0 - __half2float(hh.x));
                    ll.y = __float2half(v1 - __half2float(hh.y));
                    *reinterpret_cast<__half2*>(Olo + o) = ll;
                }
            }
        }
    }
}

#define SMEM_BN128 (3 * (256 + 256) * 80)
#define SMEM_BN64  (3 * (256 + 128) * 80)

// ---------------- fp32 SGEMM (repair path + tiny decoder) ----------------
template<bool RELU>
__global__ __launch_bounds__(256)
void sgemm_f32(const float* __restrict__ A, const float* __restrict__ B,
               const float* __restrict__ bias, float* __restrict__ C,
               const int* __restrict__ rowmap, const int* __restrict__ nf_ptr,
               int N, int K)
{
    const int nf = *nf_ptr;
    const int row0 = blockIdx.y * 128;
    if (row0 >= nf) return;

    __shared__ float As[16][128];
    __shared__ float Bs[16][128];
    const int tid  = threadIdx.x;
    const int col0 = blockIdx.x * 128;
    const int ty = tid >> 4;
    const int tx = tid & 15;

    float acc[8][8];
#pragma unroll
    for (int i = 0; i < 8; i++)
#pragma unroll
        for (int j = 0; j < 8; j++) acc[i][j] = 0.f;

    for (int k0 = 0; k0 < K; k0 += 16) {
#pragma unroll
        for (int i = 0; i < 2; i++) {
            int f4 = tid + 256 * i;
            int r  = f4 >> 2;
            int kk = (f4 & 3) << 2;
            int rr = row0 + r;
            if (rr >= nf) rr = nf - 1;
            int arow = rowmap ? rowmap[rr] : rr;
            const float4 v = *reinterpret_cast<const float4*>(
                A + (size_t)arow * K + k0 + kk);
            As[kk + 0][r] = v.x; As[kk + 1][r] = v.y;
            As[kk + 2][r] = v.z; As[kk + 3][r] = v.w;
        }
#pragma unroll
        for (int i = 0; i < 2; i++) {
            int f4 = tid + 256 * i;
            int r  = f4 >> 5;
            int cc = (f4 & 31) << 2;
            float4 v = make_float4(0.f, 0.f, 0.f, 0.f);
            if (col0 + cc < N)
                v = *reinterpret_cast<const float4*>(B + (size_t)(k0 + r) * N + col0 + cc);
            *reinterpret_cast<float4*>(&Bs[r][cc]) = v;
        }
        __syncthreads();
#pragma unroll
        for (int kk = 0; kk < 16; kk++) {
            float a[8], b[8];
#pragma unroll
            for (int i = 0; i < 8; i++) a[i] = As[kk][ty * 8 + i];
#pragma unroll
            for (int j = 0; j < 8; j++) b[j] = Bs[kk][tx * 8 + j];
#pragma unroll
            for (int i = 0; i < 8; i++)
#pragma unroll
                for (int j = 0; j < 8; j++)
                    acc[i][j] = fmaf(a[i], b[j], acc[i][j]);
        }
        __syncthreads();
    }
#pragma unroll
    for (int i = 0; i < 8; i++) {
        const size_t r = (size_t)(row0 + ty * 8 + i);
#pragma unroll
        for (int j = 0; j < 8; j += 4) {
            int c = col0 + tx * 8 + j;
            if (c < N) {
                float4 v;
                v.x = acc[i][j + 0] + bias[c + 0];
                v.y = acc[i][j + 1] + bias[c + 1];
                v.z = acc[i][j + 2] + bias[c + 2];
                v.w = acc[i][j + 3] + bias[c + 3];
                if (RELU) {
                    v.x = fmaxf(v.x, 0.f); v.y = fmaxf(v.y, 0.f);
                    v.z = fmaxf(v.z, 0.f); v.w = fmaxf(v.w, 0.f);
                }
                *reinterpret_cast<float4*>(C + r * N + c) = v;
            }
        }
    }
}

// out[row,:] = dec3[idx[row],:]
__global__ void gather_out(float* __restrict__ out) {
    size_t total = (size_t)N_ROWS * (D_IN / 4);
    for (size_t i = (size_t)blockIdx.x * blockDim.x + threadIdx.x; i < total;
         i += (size_t)gridDim.x * blockDim.x) {
        int row = (int)(i / (D_IN / 4));
        int c4  = (int)(i % (D_IN / 4));
        int bi  = g_idx[row];
        float4 v = *reinterpret_cast<const float4*>(g_dec3 + (size_t)bi * D_IN + c4 * 4);
        *reinterpret_cast<float4*>(out + (size_t)row * D_IN + c4 * 4) = v;
    }
}

// ---------------- reduction helper ----------------
__device__ double block_reduce_sum(double v) {
    __shared__ double sh[32];
    int lane = threadIdx.x & 31, w = threadIdx.x >> 5;
#pragma unroll
    for (int o = 16; o > 0; o >>= 1) v += __shfl_down_sync(0xffffffffu, v, o);
    if (lane == 0) sh[w] = v;
    __syncthreads();
    int nw = (blockDim.x + 31) >> 5;
    v = (threadIdx.x < nw) ? sh[threadIdx.x] : 0.0;
    if (w == 0)
#pragma unroll
        for (int o = 16; o > 0; o >>= 1) v += __shfl_down_sync(0xffffffffu, v, o);
    return v;
}

// ---------------- small kernels ----------------
__global__ void init_kernel() {
    int t = threadIdx.x;
    if (t < 4) g_acc[t] = 0.0;
    if (t < N_CODE) g_cnt[t] = 0;
    if (t == 0) g_nflag = 0;
}

// VQ pass 1: approx argmin; flag small-margin rows for exact fp32 repair.
__global__ __launch_bounds__(128)
void vq_kernel(const float* __restrict__ cb, float* __restrict__ out_idx,
               float* __restrict__ out_xq)
{
    __shared__ float scc[N_CODE];
    int tid = threadIdx.x;
    for (int c = tid; c < N_CODE; c += 128) {
        float s = 0.f;
#pragma unroll
        for (int e = 0; e < D_E; e++) { float w = cb[c * D_E + e]; s = fmaf(w, w, s); }
        scc[c] = s;
    }
    __syncthreads();

    float ccmax = 0.f;
    for (int c = 0; c < N_CODE; c++) ccmax = fmaxf(ccmax, scc[c]);

    int row = blockIdx.x * 128 + tid;
    float zr[D_E];
    float zz = 0.f;
#pragma unroll
    for (int e = 0; e < D_E; e++) {
        zr[e] = g_z[(size_t)row * D_E + e];
        zz = fmaf(zr[e], zr[e], zz);
    }
    float best = 3.4e38f, sec = 3.4e38f; int bi = 0;
    for (int c = 0; c < N_CODE; c++) {
        float dot = 0.f;
#pragma unroll
        for (int e = 0; e < D_E; e++) dot = fmaf(zr[e], __ldg(cb + c * D_E + e), dot);
        float d = zz - 2.f * dot + scc[c];
        if (d < best) { sec = best; best = d; bi = c; }
        else if (d < sec) sec = d;
    }

    float nz = sqrtf(zz), cmax = sqrtf(ccmax);
    float thresh = FLAG_EPS * nz * (nz + cmax) + 1e-7f;
    bool flagged = (sec - best) < thresh;

    float vq = 0.f;
    if (flagged) {
        int pos = atomicAdd(&g_nflag, 1);
        g_rowlist[pos] = row;
    } else {
        g_idx[row]   = bi;
        out_idx[row] = (float)bi;
#pragma unroll
        for (int e = 0; e < D_E; e++) {
            float xq = __ldg(cb + bi * D_E + e);
            out_xq[(size_t)row * D_E + e] = xq;
            float df = xq - zr[e];
            vq = fmaf(df, df, vq);
        }
        atomicAdd(&g_cnt[bi], 1);
    }
    double t = block_reduce_sum((double)vq);
    if (tid == 0) atomicAdd(&g_acc[0], t);
}

// VQ pass 2: flagged rows via exact fp32 z.
__global__ __launch_bounds__(256)
void repair_kernel(const float* __restrict__ cb, float* __restrict__ out_idx,
                   float* __restrict__ out_xq)
{
    __shared__ float zrow[D_E];
    __shared__ float dsh[N_CODE];
    __shared__ int   rwin;
    int tid = threadIdx.x;
    int nf = g_nflag;
    for (int i = blockIdx.x; i < nf; i += gridDim.x) {
        int row = g_rowlist[i];
        if (tid < D_E) zrow[tid] = g_zg[(size_t)i * D_E + tid];
        __syncthreads();
        float zz = 0.f;
#pragma unroll
        for (int e = 0; e < D_E; e++) zz = fmaf(zrow[e], zrow[e], zz);
        {
            int c = tid;
            float dot = 0.f, cc = 0.f;
#pragma unroll
            for (int e = 0; e < D_E; e++) {
                float w = __ldg(cb + c * D_E + e);
                dot = fmaf(zrow[e], w, dot);
                cc  = fmaf(w, w, cc);
            }
            dsh[c] = zz - 2.f * dot + cc;
        }
        __syncthreads();
        if (tid == 0) {
            float best = dsh[0]; int bi = 0;
            for (int c = 1; c < N_CODE; c++)
                if (dsh[c] < best) { best = dsh[c]; bi = c; }
            rwin = bi;
            g_idx[row] = bi;
            out_idx[row] = (float)bi;
            atomicAdd(&g_cnt[bi], 1);
        }
        __syncthreads();
        int bi = rwin;
        if (tid < D_E) {
            int e = tid;
            out_xq[(size_t)row * D_E + e] = __ldg(cb + bi * D_E + e);
            g_z[(size_t)row * D_E + e] = zrow[e];   // exact z for cos/trip
        }
        if (tid == 0) {
            float vq = 0.f;
#pragma unroll
            for (int e = 0; e < D_E; e++) {
                float df = __ldg(cb + bi * D_E + e) - zrow[e];
                vq = fmaf(df, df, vq);
            }
            atomicAdd(&g_acc[0], (double)vq);
        }
        __syncthreads();
    }
}

__global__ __launch_bounds__(256)
void cos_kernel(const float* __restrict__ qdw) {
    int row = blockIdx.x * 256 + threadIdx.x;
    float dzq = 0.f, nz = 0.f, nq = 0.f;
#pragma unroll
    for (int e = 0; e < D_E; e++) {
        float zv = g_z [(size_t)row * D_E + e];
        float qv = g_qz[(size_t)row * D_E + e];
        dzq = fmaf(zv, qv, dzq);
        nz  = fmaf(zv, zv, nz);
        nq  = fmaf(qv, qv, nq);
    }
    float cosv = dzq / fmaxf(sqrtf(nz) * sqrtf(nq), 1e-8f);
    double t = block_reduce_sum((double)(qdw[row] * cosv));
    if (threadIdx.x == 0) atomicAdd(&g_acc[1], t);
}

__global__ __launch_bounds__(256)
void trip_kernel(const int* __restrict__ tr) {
    int t = blockIdx.x * 256 + threadIdx.x;
    double v = 0.0;
    if (t < N_TRIP) {
        int a = tr[3 * t], p = tr[3 * t + 1], n = tr[3 * t + 2];
        float sp = 0.f, sn = 0.f;
#pragma unroll
        for (int e = 0; e < D_E; e++) {
            float av = g_z[(size_t)a * D_E + e];
            float d1 = av - g_z[(size_t)p * D_E + e]; sp = fmaf(d1, d1, sp);
            float d2 = av - g_z[(size_t)n * D_E + e]; sn = fmaf(d2, d2, sn);
        }
        v = (double)fmaxf(sqrtf(sp + 1e-12f) - sqrtf(sn + 1e-12f) + 0.2f, 0.f);
    }
    double s = block_reduce_sum(v);
    if (threadIdx.x == 0) atomicAdd(&g_acc[2], s);
}

// Exact contrastive shortcut: xn rows take 256 values (normalized codebook).
__global__ __launch_bounds__(256)
void code_stats(const float* __restrict__ cb) {
    int c = threadIdx.x;
    float myrow[D_E];
    float nrm = 0.f;
#pragma unroll
    for (int e = 0; e < D_E; e++) {
        myrow[e] = cb[c * D_E + e];
        nrm = fmaf(myrow[e], myrow[e], nrm);
    }
    nrm = fmaxf(sqrtf(nrm), 1e-12f);
#pragma unroll
    for (int e = 0; e < D_E; e++) { myrow[e] /= nrm; g_cbn[c * D_E + e] = myrow[e]; }
    __syncthreads();

    float m = -3.4e38f;
    for (int c2 = 0; c2 < N_CODE; c2++) {
        float dot = 0.f;
#pragma unroll
        for (int e = 0; e < D_E; e++) dot = fmaf(myrow[e], g_cbn[c2 * D_E + e], dot);
        float g = dot * 10.f;
        g_G[c * N_CODE + c2] = g;
        if (g_cnt[c2] > 0 && g > m) m = g;
    }
    double s = 0.0;
    for (int c2 = 0; c2 < N_CODE; c2++) {
        int cnt = g_cnt[c2];
        if (cnt > 0) s += (double)cnt * (double)expf(g_G[c * N_CODE + c2] - m);
    }
    g_lse[c] = m + (float)log(s);
}

__global__ __launch_bounds__(256)
void pair_kernel(const int* __restrict__ pr) {
    int k = blockIdx.x * 256 + threadIdx.x;
    double v = 0.0;
    if (k < N_PAIR) {
        int ca = g_idx[pr[2 * k]];
        int cb2 = g_idx[pr[2 * k + 1]];
        v = (double)(g_lse[ca] - g_G[ca * N_CODE + cb2]);
    }
    double s = block_reduce_sum(v);
    if (threadIdx.x == 0) atomicAdd(&g_acc[3], s);
}

__global__ void finalize_kernel(float* __restrict__ out) {
    out[VQ_OFF]    = (float)(g_acc[0] * 1.001 / ((double)N_ROWS * D_E));
    out[OUTER_OFF] = (float)(g_acc[3] / (double)N_PAIR);
    out[TRIP_OFF]  = (float)(g_acc[2] / (double)N_TRIP);
    out[QD_OFF]    = (float)(1.0 - g_acc[1] / (double)N_ROWS);
}

// ---------------- launch ----------------
extern "C" void kernel_launch(void* const* d_in, const int* in_sizes, int n_in,
                              void* d_out, int out_size)
{
    const float* x    = (const float*)d_in[0];
    const float* qe   = (const float*)d_in[1];
    const float* qdw  = (const float*)d_in[2];
    const int*   prs  = (const int*)  d_in[3];
    const int*   trs  = (const int*)  d_in[4];
    const float* ew0  = (const float*)d_in[5];
    const float* eb0  = (const float*)d_in[6];
    const float* ew1  = (const float*)d_in[7];
    const float* eb1  = (const float*)d_in[8];
    const float* ew2  = (const float*)d_in[9];
    const float* eb2  = (const float*)d_in[10];
    const float* dw0  = (const float*)d_in[11];
    const float* db0  = (const float*)d_in[12];
    const float* dw1  = (const float*)d_in[13];
    const float* db1  = (const float*)d_in[14];
    const float* dw2  = (const float*)d_in[15];
    const float* db2  = (const float*)d_in[16];
    const float* cb   = (const float*)d_in[17];
    float* out = (float*)d_out;

    cudaFuncSetAttribute(gemm_mma<128, true,  1, 3>, cudaFuncAttributeMaxDynamicSharedMemorySize, SMEM_BN128);
    cudaFuncSetAttribute(gemm_mma<64,  false, 0, 3>, cudaFuncAttributeMaxDynamicSharedMemorySize, SMEM_BN64);
    cudaFuncSetAttribute(gemm_mma<128, true,  1, 2>, cudaFuncAttributeMaxDynamicSharedMemorySize, SMEM_BN128);
    cudaFuncSetAttribute(gemm_mma<64,  false, 0, 2>, cudaFuncAttributeMaxDynamicSharedMemorySize, SMEM_BN64);

    __half *wh, *wl, *a0h, *a0l, *a1h, *a1l;
    float *z, *qz, *zg, *rep1, *rep2, *dec1, *dec2, *dec3;
    int *rowlist, *nflag, *m256;
    cudaGetSymbolAddress((void**)&wh,  g_wh);
    cudaGetSymbolAddress((void**)&wl,  g_wl);
    cudaGetSymbolAddress((void**)&a0h, g_a0h);
    cudaGetSymbolAddress((void**)&a0l, g_a0l);
    cudaGetSymbolAddress((void**)&a1h, g_a1h);
    cudaGetSymbolAddress((void**)&a1l, g_a1l);
    cudaGetSymbolAddress((void**)&z,   g_z);
    cudaGetSymbolAddress((void**)&qz,  g_qz);
    cudaGetSymbolAddress((void**)&zg,  g_zg);
    cudaGetSymbolAddress((void**)&rep1, g_rep1);
    cudaGetSymbolAddress((void**)&rep2, g_rep2);
    cudaGetSymbolAddress((void**)&dec1, g_dec1);
    cudaGetSymbolAddress((void**)&dec2, g_dec2);
    cudaGetSymbolAddress((void**)&dec3, g_dec3);
    cudaGetSymbolAddress((void**)&rowlist, g_rowlist);
    cudaGetSymbolAddress((void**)&nflag,   g_nflag);
    cudaGetSymbolAddress((void**)&m256,    g_m256);

    init_kernel<<<1, 256>>>();

    // encoder weight transpose + split (decoder weights used raw by fp32 sgemm)
    wprep_kernel<<<dim3(D_H1 / 32, D_IN / 32), 256>>>(ew0, wh + W0_OFF, wl + W0_OFF, D_IN, D_H1);
    wprep_kernel<<<dim3(D_H2 / 32, D_H1 / 32), 256>>>(ew1, wh + W1_OFF, wl + W1_OFF, D_H1, D_H2);
    wprep_kernel<<<dim3(D_E  / 32, D_H2 / 32), 256>>>(ew2, wh + W2_OFF, wl + W2_OFF, D_H2, D_E);

    // ---- decoder on 256 codebook rows (exact fp32), independent of encoder ----
    sgemm_f32<true ><<<dim3( 8, 2), 256>>>(cb,   dw0, db0, dec1, nullptr, m256, D_H2, D_E);
    sgemm_f32<true ><<<dim3(16, 2), 256>>>(dec1, dw1, db1, dec2, nullptr, m256, D_H1, D_H2);
    sgemm_f32<false><<<dim3( 6, 2), 256>>>(dec2, dw2, db2, dec3, nullptr, m256, D_IN, D_H1);

    // ---- encoder(x), 3-term ----
    split_kernel<<<2048, 256>>>(x, a0h, a0l, (size_t)N_ROWS * D_IN);
    gemm_mma<128, true,  1, 3><<<dim3(16, 256), 256, SMEM_BN128>>>(a0h, a0l, wh + W0_OFF, wl + W0_OFF, eb0, nullptr, a1h, a1l, D_H1, D_IN);
    gemm_mma<128, true,  1, 3><<<dim3( 8, 256), 256, SMEM_BN128>>>(a1h, a1l, wh + W1_OFF, wl + W1_OFF, eb1, nullptr, a0h, a0l, D_H2, D_H1);
    gemm_mma<64,  false, 0, 3><<<dim3( 1, 256), 256, SMEM_BN64 >>>(a0h, a0l, wh + W2_OFF, wl + W2_OFF, eb2, z, nullptr, nullptr, D_E, D_H2);

    // ---- VQ pass 1 + exact repair of flagged rows ----
    vq_kernel<<<256, 128>>>(cb, out + IDX_OFF, out + XQ_OFF);
    sgemm_f32<true ><<<dim3(16, 256), 256>>>(x,    ew0, eb0, rep1, rowlist, nflag, D_H1, D_IN);
    sgemm_f32<true ><<<dim3( 8, 256), 256>>>(rep1, ew1, eb1, rep2, nullptr, nflag, D_H2, D_H1);
    sgemm_f32<false><<<dim3( 1, 256), 256>>>(rep2, ew2, eb2, zg,   nullptr, nflag, D_E,  D_H2);
    repair_kernel<<<512, 256>>>(cb, out + IDX_OFF, out + XQ_OFF);

    // ---- encoder(q_embs), 2-term (qz only feeds the averaged cos loss) ----
    split_kernel<<<2048, 256>>>(qe, a0h, a0l, (size_t)N_ROWS * D_IN);
    gemm_mma<128, true,  1, 2><<<dim3(16, 256), 256, SMEM_BN128>>>(a0h, a0l, wh + W0_OFF, wl + W0_OFF, eb0, nullptr, a1h, a1l, D_H1, D_IN);
    gemm_mma<128, true,  1, 2><<<dim3( 8, 256), 256, SMEM_BN128>>>(a1h, a1l, wh + W1_OFF, wl + W1_OFF, eb1, nullptr, a0h, a0l, D_H2, D_H1);
    gemm_mma<64,  false, 0, 2><<<dim3( 1, 256), 256, SMEM_BN64 >>>(a0h, a0l, wh + W2_OFF, wl + W2_OFF, eb2, qz, nullptr, nullptr, D_E, D_H2);

    // ---- losses ----
    cos_kernel<<<128, 256>>>(qdw);
    trip_kernel<<<32, 256>>>(trs);
    code_stats<<<1, 256>>>(cb);
    pair_kernel<<<16, 256>>>(prs);

    // ---- out = dec3[idx] ----
    gather_out<<<2048, 256>>>(out);

    finalize_kernel<<<1, 1>>>(out);
}

// round 6
// speedup vs baseline: 4.5918x; 1.3265x over previous
#include <cuda_runtime.h>
#include <cuda_fp16.h>
#include <math.h>
#include <stdint.h>

#define N_ROWS 32768
#define D_IN   768
#define D_H1   2048
#define D_H2   1024
#define D_E    64
#define N_CODE 256
#define N_PAIR 4096
#define N_TRIP 8192

#define VQ_OFF    25165824
#define IDX_OFF   25165825
#define XQ_OFF    25198593
#define OUTER_OFF 27295745
#define TRIP_OFF  27295746
#define QD_OFF    27295747

#define FLAG_EPS 2e-5f

// ---------------- scratch (device globals) ----------------
// all weights [N,K] transposed, hi/lo fp16
#define W0_OFF 0          // enc_w0: N=2048,K=768
#define W1_OFF 1572864    // enc_w1: N=1024,K=2048
#define W2_OFF 3670016    // enc_w2: N=64,  K=1024
#define W3_OFF 3735552    // dec_w0: N=1024,K=64
#define W4_OFF 3801088    // dec_w1: N=2048,K=1024
#define W5_OFF 5898240    // dec_w2: N=768, K=2048
#define W_TOT  7471104
__device__ __align__(16) __half g_wh[W_TOT];
__device__ __align__(16) __half g_wl[W_TOT];

#define ACT_ELEMS ((size_t)N_ROWS * 2048)
__device__ __align__(16) __half g_a0h[ACT_ELEMS];
__device__ __align__(16) __half g_a0l[ACT_ELEMS];
__device__ __align__(16) __half g_a1h[ACT_ELEMS];
__device__ __align__(16) __half g_a1l[ACT_ELEMS];

// decoder-on-codebook buffers (M=256)
__device__ __align__(16) __half g_cbh[N_CODE * D_E];
__device__ __align__(16) __half g_cbl[N_CODE * D_E];
__device__ __align__(16) __half g_dh1[N_CODE * D_H2];
__device__ __align__(16) __half g_dl1[N_CODE * D_H2];
__device__ __align__(16) __half g_dh2[N_CODE * D_H1];
__device__ __align__(16) __half g_dl2[N_CODE * D_H1];
__device__ float g_dec3[N_CODE * D_IN];

__device__ float g_z [(size_t)N_ROWS * D_E];
__device__ float g_qz[(size_t)N_ROWS * D_E];
__device__ float g_zg[(size_t)N_ROWS * D_E];          // exact z for flagged rows
__device__ float g_rep1[(size_t)N_ROWS * D_H1];       // fp32 repair scratch
__device__ float g_rep2[(size_t)N_ROWS * D_H2];
__device__ float g_cbn[N_CODE * D_E];
__device__ float g_G  [N_CODE * N_CODE];
__device__ float g_lse[N_CODE];
__device__ int   g_idx[N_ROWS];
__device__ int   g_cnt[N_CODE];
__device__ int   g_rowlist[N_ROWS];
__device__ int   g_nflag;
__device__ double g_acc[4];

// ---------------- helpers ----------------
__device__ __forceinline__ uint32_t smem_u32(const void* p) {
    uint32_t a;
    asm("{ .reg .u64 t; cvta.to.shared.u64 t, %1; cvt.u32.u64 %0, t; }" : "=r"(a) : "l"(p));
    return a;
}
#define LDSM4(r, a) \
    asm volatile("ldmatrix.sync.aligned.m8n8.x4.shared.b16 {%0,%1,%2,%3}, [%4];" \
        : "=r"((r)[0]), "=r"((r)[1]), "=r"((r)[2]), "=r"((r)[3]) : "r"(a))
#define MMA16816(d, a, b) \
    asm volatile("mma.sync.aligned.m16n8k16.row.col.f32.f16.f16.f32 " \
        "{%0,%1,%2,%3}, {%4,%5,%6,%7}, {%8,%9}, {%0,%1,%2,%3};" \
        : "+f"((d)[0]), "+f"((d)[1]), "+f"((d)[2]), "+f"((d)[3]) \
        : "r"((a)[0]), "r"((a)[1]), "r"((a)[2]), "r"((a)[3]), "r"((b)[0]), "r"((b)[1]))
#define CP_ASYNC16(sa, ga) \
    asm volatile("cp.async.cg.shared.global [%0], [%1], 16;" :: "r"(sa), "l"(ga))

// ---------------- prep kernels ----------------
__global__ void split_kernel(const float* __restrict__ src,
                             __half* __restrict__ hi,
                             __half* __restrict__ lo, size_t n) {
    for (size_t i = (size_t)blockIdx.x * blockDim.x + threadIdx.x; i < n;
         i += (size_t)gridDim.x * blockDim.x) {
        float v = src[i];
        __half h = __float2half(v);
        hi[i] = h;
        if (lo) lo[i] = __float2half(v - __half2float(h));
    }
}

__global__ __launch_bounds__(256)
void wprep_kernel(const float* __restrict__ W,
                  __half* __restrict__ hi,
                  __half* __restrict__ lo, int K, int N) {
    __shared__ float t[32][33];
    int kb = blockIdx.y * 32, nb = blockIdx.x * 32;
    int tx = threadIdx.x & 31, ty = threadIdx.x >> 5;
#pragma unroll
    for (int j = 0; j < 32; j += 8)
        t[ty + j][tx] = W[(size_t)(kb + ty + j) * N + nb + tx];
    __syncthreads();
#pragma unroll
    for (int j = 0; j < 32; j += 8) {
        float v = t[tx][ty + j];
        size_t o = (size_t)(nb + ty + j) * K + kb + tx;
        __half h = __float2half(v);
        hi[o] = h;
        lo[o] = __float2half(v - __half2float(h));
    }
}

// ---------------- fp16 multi-term mma GEMM ----------------
// TERMS=3: AhBh+AlBh+AhBl; TERMS=2: AhBh+AlBh; TERMS=1: AhBh.
// OMODE 0: fp32 out; 1: fp16 hi/lo out; 2: fp16 hi only.
template<int BN, bool RELU, int OMODE, int TERMS>
__global__ __launch_bounds__(256, 1)
void gemm_mma(const __half* __restrict__ Ahi, const __half* __restrict__ Alo,
              const __half* __restrict__ Bhi, const __half* __restrict__ Blo,
              const float* __restrict__ bias,
              float* __restrict__ Of,
              __half* __restrict__ Ohi, __half* __restrict__ Olo,
              int Nn, int K)
{
    constexpr int WARPS_M = (BN == 128) ? 2 : 4;
    constexpr int WARPS_N = 8 / WARPS_M;
    constexpr int WM = 128 / WARPS_M;
    constexpr int WN = BN / WARPS_N;
    constexpr int MT = WM / 16;
    constexpr int NT = WN / 8;
    constexpr int ROWS = 256 + 2 * BN;
    constexpr int LROWS = (TERMS == 3) ? ROWS : ((TERMS == 2) ? (256 + BN) : (128 + BN));
    constexpr int PITCH = 80;
    constexpr int STAGE = ROWS * PITCH;
    constexpr int CH = LROWS * 4;

    extern __shared__ __align__(16) char sm[];
    const int tid  = threadIdx.x;
    const int lane = tid & 31, wid = tid >> 5;
    const int wm = wid / WARPS_N, wn = wid % WARPS_N;
    const int row0 = blockIdx.y * 128;
    const int col0 = blockIdx.x * BN;
    const uint32_t sb = smem_u32(sm);

    const uint32_t aoff = ((lane & 7) + ((lane >> 3) & 1) * 8) * PITCH + ((lane >> 4) << 4);
    const uint32_t boff = ((lane & 7) + ((lane >> 4) & 1) * 8) * PITCH + (((lane >> 3) & 1) << 4);

    const int nk = K >> 5;

    auto load_stage = [&](int i) {
        uint32_t sbase = sb + (i % 3) * STAGE;
        int k0 = i << 5;
#pragma unroll
        for (int c = tid; c < CH; c += 256) {
            int r = c >> 2, ch = c & 3;
            const __half* g;
            int srow = r;
            if (TERMS == 1) {
                if (r < 128) g = Ahi + (size_t)(row0 + r) * K;
                else { g = Bhi + (size_t)(col0 + r - 128) * K; srow = r + 128; }
            } else {
                if (r < 128)            g = Ahi + (size_t)(row0 + r) * K;
                else if (r < 256)       g = Alo + (size_t)(row0 + r - 128) * K;
                else if (r < 256 + BN)  g = Bhi + (size_t)(col0 + r - 256) * K;
                else                    g = Blo + (size_t)(col0 + r - 256 - BN) * K;
            }
            CP_ASYNC16(sbase + srow * PITCH + ch * 16, g + k0 + ch * 8);
        }
        asm volatile("cp.async.commit_group;" ::: "memory");
    };

    float acc[MT][NT][4];
#pragma unroll
    for (int mi = 0; mi < MT; mi++)
#pragma unroll
        for (int ni = 0; ni < NT; ni++)
#pragma unroll
            for (int q = 0; q < 4; q++) acc[mi][ni][q] = 0.f;

    load_stage(0);
    load_stage(1);

    for (int i = 0; i < nk; i++) {
        if (i + 1 < nk) asm volatile("cp.async.wait_group 1;" ::: "memory");
        else            asm volatile("cp.async.wait_group 0;" ::: "memory");
        __syncthreads();
        if (i + 2 < nk) load_stage(i + 2);

        uint32_t sA = sb + (i % 3) * STAGE;
        uint32_t sB = sA + 256 * PITCH;
#pragma unroll
        for (int ks = 0; ks < 2; ks++) {
            uint32_t kofs = ks * 32;
            uint32_t ah[MT][4], al[MT][4], bh[NT][2], bl[NT][2];
#pragma unroll
            for (int mi = 0; mi < MT; mi++) {
                uint32_t base = sA + (uint32_t)(wm * WM + mi * 16) * PITCH + aoff + kofs;
                LDSM4(ah[mi], base);
                if (TERMS >= 2) LDSM4(al[mi], base + 128 * PITCH);
            }
#pragma unroll
            for (int np = 0; np < NT / 2; np++) {
                uint32_t base = sB + (uint32_t)(wn * WN + np * 16) * PITCH + boff + kofs;
                uint32_t r[4];
                LDSM4(r, base);
                bh[2 * np][0] = r[0]; bh[2 * np][1] = r[1];
                bh[2 * np + 1][0] = r[2]; bh[2 * np + 1][1] = r[3];
                if (TERMS == 3) {
                    LDSM4(r, base + BN * PITCH);
                    bl[2 * np][0] = r[0]; bl[2 * np][1] = r[1];
                    bl[2 * np + 1][0] = r[2]; bl[2 * np + 1][1] = r[3];
                }
            }
#pragma unroll
            for (int mi = 0; mi < MT; mi++)
#pragma unroll
                for (int ni = 0; ni < NT; ni++) MMA16816(acc[mi][ni], ah[mi], bh[ni]);
            if (TERMS >= 2) {
#pragma unroll
                for (int mi = 0; mi < MT; mi++)
#pragma unroll
                    for (int ni = 0; ni < NT; ni++) MMA16816(acc[mi][ni], al[mi], bh[ni]);
            }
            if (TERMS == 3) {
#pragma unroll
                for (int mi = 0; mi < MT; mi++)
#pragma unroll
                    for (int ni = 0; ni < NT; ni++) MMA16816(acc[mi][ni], ah[mi], bl[ni]);
            }
        }
    }

#pragma unroll
    for (int mi = 0; mi < MT; mi++) {
        int rbase = row0 + wm * WM + mi * 16 + (lane >> 2);
#pragma unroll
        for (int ni = 0; ni < NT; ni++) {
            int c = col0 + wn * WN + ni * 8 + (lane & 3) * 2;
            float b0 = __ldg(&bias[c]), b1 = __ldg(&bias[c + 1]);
#pragma unroll
            for (int h = 0; h < 2; h++) {
                float v0 = acc[mi][ni][2 * h]     + b0;
                float v1 = acc[mi][ni][2 * h + 1] + b1;
                if (RELU) { v0 = fmaxf(v0, 0.f); v1 = fmaxf(v1, 0.f); }
                size_t o = (size_t)(rbase + 8 * h) * Nn + c;
                if (OMODE == 0) {
                    *reinterpret_cast<float2*>(Of + o) = make_float2(v0, v1);
                } else {
                    __half2 hh;
                    hh.x = __float2half(v0);
                    hh.y = __float2half(v1);
                    *reinterpret_cast<__half2*>(Ohi + o) = hh;
                    if (OMODE == 1) {
                        __half2 ll;
                        ll.x = __float2half(v0 - __half2float(hh.x));
                        ll.y = __float2half(v1 - __half2float(hh.y));
                        *reinterpret_cast<__half2*>(Olo + o) = ll;
                    }
                }
            }
        }
    }
}

#define SMEM_BN128 (3 * (256 + 256) * 80)
#define SMEM_BN64  (3 * (256 + 128) * 80)

// ---------------- fp32 small-M GEMM (repair path): BM=32, BN=64 ----------------
template<bool RELU>
__global__ __launch_bounds__(256)
void sgemm32(const float* __restrict__ A, const float* __restrict__ B,
             const float* __restrict__ bias, float* __restrict__ C,
             const int* __restrict__ rowmap, const int* __restrict__ nf_ptr,
             int N, int K)
{
    const int nf = *nf_ptr;
    const int row0 = blockIdx.y * 32;
    if (row0 >= nf) return;

    __shared__ float As[32][33];
    __shared__ float Bs[32][64];
    const int tid = threadIdx.x;
    const int ty = tid >> 4;       // 0..15: rows ty*2, ty*2+1
    const int tx = tid & 15;       // cols tx*4..+3
    const int col0 = blockIdx.x * 64;

    float acc[2][4] = {{0.f,0.f,0.f,0.f},{0.f,0.f,0.f,0.f}};

    for (int k0 = 0; k0 < K; k0 += 32) {
        {   // A tile: 32 rows x 32 k, one float4 per thread
            int r  = tid >> 3;
            int kc = (tid & 7) << 2;
            int rr = row0 + r;
            if (rr >= nf) rr = nf - 1;
            int arow = rowmap ? rowmap[rr] : rr;
            float4 v = *reinterpret_cast<const float4*>(A + (size_t)arow * K + k0 + kc);
            As[r][kc] = v.x; As[r][kc + 1] = v.y; As[r][kc + 2] = v.z; As[r][kc + 3] = v.w;
        }
        {   // B tile: 32 k x 64 n, two float4 per thread
#pragma unroll
            for (int it = 0; it < 2; it++) {
                int f4 = tid + 256 * it;      // 0..511
                int r  = f4 >> 4;             // 0..31
                int cc = (f4 & 15) << 2;      // 0..60
                float4 v = *reinterpret_cast<const float4*>(B + (size_t)(k0 + r) * N + col0 + cc);
                *reinterpret_cast<float4*>(&Bs[r][cc]) = v;
            }
        }
        __syncthreads();
#pragma unroll
        for (int kk = 0; kk < 32; kk++) {
            float a0 = As[ty * 2][kk], a1 = As[ty * 2 + 1][kk];
            float b0 = Bs[kk][tx * 4], b1 = Bs[kk][tx * 4 + 1];
            float b2 = Bs[kk][tx * 4 + 2], b3 = Bs[kk][tx * 4 + 3];
            acc[0][0] = fmaf(a0, b0, acc[0][0]); acc[0][1] = fmaf(a0, b1, acc[0][1]);
            acc[0][2] = fmaf(a0, b2, acc[0][2]); acc[0][3] = fmaf(a0, b3, acc[0][3]);
            acc[1][0] = fmaf(a1, b0, acc[1][0]); acc[1][1] = fmaf(a1, b1, acc[1][1]);
            acc[1][2] = fmaf(a1, b2, acc[1][2]); acc[1][3] = fmaf(a1, b3, acc[1][3]);
        }
        __syncthreads();
    }
#pragma unroll
    for (int h = 0; h < 2; h++) {
        int r = row0 + ty * 2 + h;
        int c = col0 + tx * 4;
        float4 v;
        v.x = acc[h][0] + bias[c];     v.y = acc[h][1] + bias[c + 1];
        v.z = acc[h][2] + bias[c + 2]; v.w = acc[h][3] + bias[c + 3];
        if (RELU) {
            v.x = fmaxf(v.x, 0.f); v.y = fmaxf(v.y, 0.f);
            v.z = fmaxf(v.z, 0.f); v.w = fmaxf(v.w, 0.f);
        }
        *reinterpret_cast<float4*>(C + (size_t)r * N + c) = v;
    }
}

// out[row,:] = dec3[idx[row],:]
__global__ void gather_out(float* __restrict__ out) {
    size_t total = (size_t)N_ROWS * (D_IN / 4);
    for (size_t i = (size_t)blockIdx.x * blockDim.x + threadIdx.x; i < total;
         i += (size_t)gridDim.x * blockDim.x) {
        int row = (int)(i / (D_IN / 4));
        int c4  = (int)(i % (D_IN / 4));
        int bi  = g_idx[row];
        float4 v = *reinterpret_cast<const float4*>(g_dec3 + (size_t)bi * D_IN + c4 * 4);
        *reinterpret_cast<float4*>(out + (size_t)row * D_IN + c4 * 4) = v;
    }
}

// ---------------- reduction helper ----------------
__device__ double block_reduce_sum(double v) {
    __shared__ double sh[32];
    int lane = threadIdx.x & 31, w = threadIdx.x >> 5;
#pragma unroll
    for (int o = 16; o > 0; o >>= 1) v += __shfl_down_sync(0xffffffffu, v, o);
    if (lane == 0) sh[w] = v;
    __syncthreads();
    int nw = (blockDim.x + 31) >> 5;
    v = (threadIdx.x < nw) ? sh[threadIdx.x] : 0.0;
    if (w == 0)
#pragma unroll
        for (int o = 16; o > 0; o >>= 1) v += __shfl_down_sync(0xffffffffu, v, o);
    return v;
}

// ---------------- small kernels ----------------
__global__ void init_kernel() {
    int t = threadIdx.x;
    if (t < 4) g_acc[t] = 0.0;
    if (t < N_CODE) g_cnt[t] = 0;
    if (t == 0) g_nflag = 0;
}

// VQ pass 1: approx argmin; flag small-margin rows for exact fp32 repair.
__global__ __launch_bounds__(128)
void vq_kernel(const float* __restrict__ cb, float* __restrict__ out_idx,
               float* __restrict__ out_xq)
{
    __shared__ float scc[N_CODE];
    int tid = threadIdx.x;
    for (int c = tid; c < N_CODE; c += 128) {
        float s = 0.f;
#pragma unroll
        for (int e = 0; e < D_E; e++) { float w = cb[c * D_E + e]; s = fmaf(w, w, s); }
        scc[c] = s;
    }
    __syncthreads();

    float ccmax = 0.f;
    for (int c = 0; c < N_CODE; c++) ccmax = fmaxf(ccmax, scc[c]);

    int row = blockIdx.x * 128 + tid;
    float zr[D_E];
    float zz = 0.f;
#pragma unroll
    for (int e = 0; e < D_E; e++) {
        zr[e] = g_z[(size_t)row * D_E + e];
        zz = fmaf(zr[e], zr[e], zz);
    }
    float best = 3.4e38f, sec = 3.4e38f; int bi = 0;
    for (int c = 0; c < N_CODE; c++) {
        float dot = 0.f;
#pragma unroll
        for (int e = 0; e < D_E; e++) dot = fmaf(zr[e], __ldg(cb + c * D_E + e), dot);
        float d = zz - 2.f * dot + scc[c];
        if (d < best) { sec = best; best = d; bi = c; }
        else if (d < sec) sec = d;
    }

    float nz = sqrtf(zz), cmax = sqrtf(ccmax);
    float thresh = FLAG_EPS * nz * (nz + cmax) + 1e-7f;
    bool flagged = (sec - best) < thresh;

    float vq = 0.f;
    if (flagged) {
        int pos = atomicAdd(&g_nflag, 1);
        g_rowlist[pos] = row;
    } else {
        g_idx[row]   = bi;
        out_idx[row] = (float)bi;
#pragma unroll
        for (int e = 0; e < D_E; e++) {
            float xq = __ldg(cb + bi * D_E + e);
            out_xq[(size_t)row * D_E + e] = xq;
            float df = xq - zr[e];
            vq = fmaf(df, df, vq);
        }
        atomicAdd(&g_cnt[bi], 1);
    }
    double t = block_reduce_sum((double)vq);
    if (tid == 0) atomicAdd(&g_acc[0], t);
}

// VQ pass 2: flagged rows via exact fp32 z.
__global__ __launch_bounds__(256)
void repair_kernel(const float* __restrict__ cb, float* __restrict__ out_idx,
                   float* __restrict__ out_xq)
{
    __shared__ float zrow[D_E];
    __shared__ float dsh[N_CODE];
    __shared__ int   rwin;
    int tid = threadIdx.x;
    int nf = g_nflag;
    for (int i = blockIdx.x; i < nf; i += gridDim.x) {
        int row = g_rowlist[i];
        if (tid < D_E) zrow[tid] = g_zg[(size_t)i * D_E + tid];
        __syncthreads();
        float zz = 0.f;
#pragma unroll
        for (int e = 0; e < D_E; e++) zz = fmaf(zrow[e], zrow[e], zz);
        {
            int c = tid;
            float dot = 0.f, cc = 0.f;
#pragma unroll
            for (int e = 0; e < D_E; e++) {
                float w = __ldg(cb + c * D_E + e);
                dot = fmaf(zrow[e], w, dot);
                cc  = fmaf(w, w, cc);
            }
            dsh[c] = zz - 2.f * dot + cc;
        }
        __syncthreads();
        if (tid == 0) {
            float best = dsh[0]; int bi = 0;
            for (int c = 1; c < N_CODE; c++)
                if (dsh[c] < best) { best = dsh[c]; bi = c; }
            rwin = bi;
            g_idx[row] = bi;
            out_idx[row] = (float)bi;
            atomicAdd(&g_cnt[bi], 1);
        }
        __syncthreads();
        int bi = rwin;
        if (tid < D_E) {
            int e = tid;
            out_xq[(size_t)row * D_E + e] = __ldg(cb + bi * D_E + e);
            g_z[(size_t)row * D_E + e] = zrow[e];   // exact z for cos/trip
        }
        if (tid == 0) {
            float vq = 0.f;
#pragma unroll
            for (int e = 0; e < D_E; e++) {
                float df = __ldg(cb + bi * D_E + e) - zrow[e];
                vq = fmaf(df, df, vq);
            }
            atomicAdd(&g_acc[0], (double)vq);
        }
        __syncthreads();
    }
}

__global__ __launch_bounds__(256)
void cos_kernel(const float* __restrict__ qdw) {
    int row = blockIdx.x * 256 + threadIdx.x;
    float dzq = 0.f, nz = 0.f, nq = 0.f;
#pragma unroll
    for (int e = 0; e < D_E; e++) {
        float zv = g_z [(size_t)row * D_E + e];
        float qv = g_qz[(size_t)row * D_E + e];
        dzq = fmaf(zv, qv, dzq);
        nz  = fmaf(zv, zv, nz);
        nq  = fmaf(qv, qv, nq);
    }
    float cosv = dzq / fmaxf(sqrtf(nz) * sqrtf(nq), 1e-8f);
    double t = block_reduce_sum((double)(qdw[row] * cosv));
    if (threadIdx.x == 0) atomicAdd(&g_acc[1], t);
}

__global__ __launch_bounds__(256)
void trip_kernel(const int* __restrict__ tr) {
    int t = blockIdx.x * 256 + threadIdx.x;
    double v = 0.0;
    if (t < N_TRIP) {
        int a = tr[3 * t], p = tr[3 * t + 1], n = tr[3 * t + 2];
        float sp = 0.f, sn = 0.f;
#pragma unroll
        for (int e = 0; e < D_E; e++) {
            float av = g_z[(size_t)a * D_E + e];
            float d1 = av - g_z[(size_t)p * D_E + e]; sp = fmaf(d1, d1, sp);
            float d2 = av - g_z[(size_t)n * D_E + e]; sn = fmaf(d2, d2, sn);
        }
        v = (double)fmaxf(sqrtf(sp + 1e-12f) - sqrtf(sn + 1e-12f) + 0.2f, 0.f);
    }
    double s = block_reduce_sum(v);
    if (threadIdx.x == 0) atomicAdd(&g_acc[2], s);
}

// Exact contrastive shortcut: xn rows take 256 values (normalized codebook).
__global__ __launch_bounds__(256)
void code_stats(const float* __restrict__ cb) {
    int c = threadIdx.x;
    float myrow[D_E];
    float nrm = 0.f;
#pragma unroll
    for (int e = 0; e < D_E; e++) {
        myrow[e] = cb[c * D_E + e];
        nrm = fmaf(myrow[e], myrow[e], nrm);
    }
    nrm = fmaxf(sqrtf(nrm), 1e-12f);
#pragma unroll
    for (int e = 0; e < D_E; e++) { myrow[e] /= nrm; g_cbn[c * D_E + e] = myrow[e]; }
    __syncthreads();

    float m = -3.4e38f;
    for (int c2 = 0; c2 < N_CODE; c2++) {
        float dot = 0.f;
#pragma unroll
        for (int e = 0; e < D_E; e++) dot = fmaf(myrow[e], g_cbn[c2 * D_E + e], dot);
        float g = dot * 10.f;
        g_G[c * N_CODE + c2] = g;
        if (g_cnt[c2] > 0 && g > m) m = g;
    }
    double s = 0.0;
    for (int c2 = 0; c2 < N_CODE; c2++) {
        int cnt = g_cnt[c2];
        if (cnt > 0) s += (double)cnt * (double)expf(g_G[c * N_CODE + c2] - m);
    }
    g_lse[c] = m + (float)log(s);
}

__global__ __launch_bounds__(256)
void pair_kernel(const int* __restrict__ pr) {
    int k = blockIdx.x * 256 + threadIdx.x;
    double v = 0.0;
    if (k < N_PAIR) {
        int ca = g_idx[pr[2 * k]];
        int cb2 = g_idx[pr[2 * k + 1]];
        v = (double)(g_lse[ca] - g_G[ca * N_CODE + cb2]);
    }
    double s = block_reduce_sum(v);
    if (threadIdx.x == 0) atomicAdd(&g_acc[3], s);
}

__global__ void finalize_kernel(float* __restrict__ out) {
    out[VQ_OFF]    = (float)(g_acc[0] * 1.001 / ((double)N_ROWS * D_E));
    out[OUTER_OFF] = (float)(g_acc[3] / (double)N_PAIR);
    out[TRIP_OFF]  = (float)(g_acc[2] / (double)N_TRIP);
    out[QD_OFF]    = (float)(1.0 - g_acc[1] / (double)N_ROWS);
}

// ---------------- launch ----------------
extern "C" void kernel_launch(void* const* d_in, const int* in_sizes, int n_in,
                              void* d_out, int out_size)
{
    const float* x    = (const float*)d_in[0];
    const float* qe   = (const float*)d_in[1];
    const float* qdw  = (const float*)d_in[2];
    const int*   prs  = (const int*)  d_in[3];
    const int*   trs  = (const int*)  d_in[4];
    const float* ew0  = (const float*)d_in[5];
    const float* eb0  = (const float*)d_in[6];
    const float* ew1  = (const float*)d_in[7];
    const float* eb1  = (const float*)d_in[8];
    const float* ew2  = (const float*)d_in[9];
    const float* eb2  = (const float*)d_in[10];
    const float* dw0  = (const float*)d_in[11];
    const float* db0  = (const float*)d_in[12];
    const float* dw1  = (const float*)d_in[13];
    const float* db1  = (const float*)d_in[14];
    const float* dw2  = (const float*)d_in[15];
    const float* db2  = (const float*)d_in[16];
    const float* cb   = (const float*)d_in[17];
    float* out = (float*)d_out;

    cudaFuncSetAttribute(gemm_mma<128, true,  1, 3>, cudaFuncAttributeMaxDynamicSharedMemorySize, SMEM_BN128);
    cudaFuncSetAttribute(gemm_mma<128, false, 0, 3>, cudaFuncAttributeMaxDynamicSharedMemorySize, SMEM_BN128);
    cudaFuncSetAttribute(gemm_mma<64,  false, 0, 3>, cudaFuncAttributeMaxDynamicSharedMemorySize, SMEM_BN64);
    cudaFuncSetAttribute(gemm_mma<128, true,  2, 1>, cudaFuncAttributeMaxDynamicSharedMemorySize, SMEM_BN128);
    cudaFuncSetAttribute(gemm_mma<64,  false, 0, 1>, cudaFuncAttributeMaxDynamicSharedMemorySize, SMEM_BN64);

    __half *wh, *wl, *a0h, *a0l, *a1h, *a1l, *cbh, *cbl, *dh1, *dl1, *dh2, *dl2;
    float *z, *qz, *zg, *rep1, *rep2, *dec3;
    int *rowlist, *nflag;
    cudaGetSymbolAddress((void**)&wh,  g_wh);
    cudaGetSymbolAddress((void**)&wl,  g_wl);
    cudaGetSymbolAddress((void**)&a0h, g_a0h);
    cudaGetSymbolAddress((void**)&a0l, g_a0l);
    cudaGetSymbolAddress((void**)&a1h, g_a1h);
    cudaGetSymbolAddress((void**)&a1l, g_a1l);
    cudaGetSymbolAddress((void**)&cbh, g_cbh);
    cudaGetSymbolAddress((void**)&cbl, g_cbl);
    cudaGetSymbolAddress((void**)&dh1, g_dh1);
    cudaGetSymbolAddress((void**)&dl1, g_dl1);
    cudaGetSymbolAddress((void**)&dh2, g_dh2);
    cudaGetSymbolAddress((void**)&dl2, g_dl2);
    cudaGetSymbolAddress((void**)&z,   g_z);
    cudaGetSymbolAddress((void**)&qz,  g_qz);
    cudaGetSymbolAddress((void**)&zg,  g_zg);
    cudaGetSymbolAddress((void**)&rep1, g_rep1);
    cudaGetSymbolAddress((void**)&rep2, g_rep2);
    cudaGetSymbolAddress((void**)&dec3, g_dec3);
    cudaGetSymbolAddress((void**)&rowlist, g_rowlist);
    cudaGetSymbolAddress((void**)&nflag,   g_nflag);

    init_kernel<<<1, 256>>>();

    // weight transpose + split (encoder and decoder)
    wprep_kernel<<<dim3(D_H1 / 32, D_IN / 32), 256>>>(ew0, wh + W0_OFF, wl + W0_OFF, D_IN, D_H1);
    wprep_kernel<<<dim3(D_H2 / 32, D_H1 / 32), 256>>>(ew1, wh + W1_OFF, wl + W1_OFF, D_H1, D_H2);
    wprep_kernel<<<dim3(D_E  / 32, D_H2 / 32), 256>>>(ew2, wh + W2_OFF, wl + W2_OFF, D_H2, D_E);
    wprep_kernel<<<dim3(D_H2 / 32, D_E  / 32), 256>>>(dw0, wh + W3_OFF, wl + W3_OFF, D_E,  D_H2);
    wprep_kernel<<<dim3(D_H1 / 32, D_H2 / 32), 256>>>(dw1, wh + W4_OFF, wl + W4_OFF, D_H2, D_H1);
    wprep_kernel<<<dim3(D_IN / 32, D_H1 / 32), 256>>>(dw2, wh + W5_OFF, wl + W5_OFF, D_H1, D_IN);

    // ---- decoder on 256 codebook rows via 3-term fp16 mma ----
    split_kernel<<<32, 256>>>(cb, cbh, cbl, (size_t)N_CODE * D_E);
    gemm_mma<128, true,  1, 3><<<dim3( 8, 2), 256, SMEM_BN128>>>(cbh, cbl, wh + W3_OFF, wl + W3_OFF, db0, nullptr, dh1, dl1, D_H2, D_E);
    gemm_mma<128, true,  1, 3><<<dim3(16, 2), 256, SMEM_BN128>>>(dh1, dl1, wh + W4_OFF, wl + W4_OFF, db1, nullptr, dh2, dl2, D_H1, D_H2);
    gemm_mma<128, false, 0, 3><<<dim3( 6, 2), 256, SMEM_BN128>>>(dh2, dl2, wh + W5_OFF, wl + W5_OFF, db2, dec3, nullptr, nullptr, D_IN, D_H1);

    // ---- encoder(x), 3-term ----
    split_kernel<<<2048, 256>>>(x, a0h, a0l, (size_t)N_ROWS * D_IN);
    gemm_mma<128, true,  1, 3><<<dim3(16, 256), 256, SMEM_BN128>>>(a0h, a0l, wh + W0_OFF, wl + W0_OFF, eb0, nullptr, a1h, a1l, D_H1, D_IN);
    gemm_mma<128, true,  1, 3><<<dim3( 8, 256), 256, SMEM_BN128>>>(a1h, a1l, wh + W1_OFF, wl + W1_OFF, eb1, nullptr, a0h, a0l, D_H2, D_H1);
    gemm_mma<64,  false, 0, 3><<<dim3( 1, 256), 256, SMEM_BN64 >>>(a0h, a0l, wh + W2_OFF, wl + W2_OFF, eb2, z, nullptr, nullptr, D_E, D_H2);

    // ---- VQ pass 1 + exact fp32 repair of flagged rows ----
    vq_kernel<<<256, 128>>>(cb, out + IDX_OFF, out + XQ_OFF);
    sgemm32<true ><<<dim3(32, 1024), 256>>>(x,    ew0, eb0, rep1, rowlist, nflag, D_H1, D_IN);
    sgemm32<true ><<<dim3(16, 1024), 256>>>(rep1, ew1, eb1, rep2, nullptr, nflag, D_H2, D_H1);
    sgemm32<false><<<dim3( 1, 1024), 256>>>(rep2, ew2, eb2, zg,   nullptr, nflag, D_E,  D_H2);
    repair_kernel<<<512, 256>>>(cb, out + IDX_OFF, out + XQ_OFF);

    // ---- encoder(q_embs), 1-term (qz only feeds the averaged cos loss) ----
    split_kernel<<<2048, 256>>>(qe, a0h, nullptr, (size_t)N_ROWS * D_IN);
    gemm_mma<128, true,  2, 1><<<dim3(16, 256), 256, SMEM_BN128>>>(a0h, nullptr, wh + W0_OFF, nullptr, eb0, nullptr, a1h, nullptr, D_H1, D_IN);
    gemm_mma<128, true,  2, 1><<<dim3( 8, 256), 256, SMEM_BN128>>>(a1h, nullptr, wh + W1_OFF, nullptr, eb1, nullptr, a0h, nullptr, D_H2, D_H1);
    gemm_mma<64,  false, 0, 1><<<dim3( 1, 256), 256, SMEM_BN64 >>>(a0h, nullptr, wh + W2_OFF, nullptr, eb2, qz, nullptr, nullptr, D_E, D_H2);

    // ---- losses ----
    cos_kernel<<<128, 256>>>(qdw);
    trip_kernel<<<32, 256>>>(trs);
    code_stats<<<1, 256>>>(cb);
    pair_kernel<<<16, 256>>>(prs);

    // ---- out = dec3[idx] ----
    gather_out<<<2048, 256>>>(out);

    finalize_kernel<<<1, 1>>>(out);
}